// round 1
// baseline (speedup 1.0000x reference)
#include <cuda_runtime.h>
#include <math.h>

#define D_MODEL 1024
#define NHEAD 16
#define DKH 64
#define BATCH 4
#define SEQ 2048
#define MTOK (BATCH * SEQ)   // 8192

// Scratch (alloc-free rule: __device__ globals)
__device__ float g_q[BATCH * NHEAD * SEQ * DKH];     // [B,H,S,dk]
__device__ float g_k[BATCH * NHEAD * SEQ * DKH];
__device__ float g_v[BATCH * NHEAD * SEQ * DKH];
__device__ float g_attn[MTOK * D_MODEL];             // [B,S,D]

// ---------------------------------------------------------------------------
// GEMM: C[m,n] = sum_k A[m,k] * B[n,k]   (both K-major, "NT")
// M=8192, N=1024, K=1024. 128x128 tile, BK=8, 256 threads, 8x8 per thread.
// MODE 0: write head-split layout [B,H,S,dk]; MODE 1: plain [M,N].
// ---------------------------------------------------------------------------
template <int MODE>
__global__ void __launch_bounds__(256) gemm_nt_kernel(
    const float* __restrict__ A, const float* __restrict__ B,
    float* __restrict__ C)
{
    const int K = D_MODEL;
    __shared__ float As[8][128];
    __shared__ float Bs[8][128];

    const int tid  = threadIdx.x;
    const int bm   = blockIdx.y * 128;
    const int bn   = blockIdx.x * 128;
    const int lrow = tid >> 1;          // 0..127
    const int lcol = (tid & 1) << 2;    // 0 or 4
    const int ty   = tid >> 4;          // 0..15
    const int tx   = tid & 15;          // 0..15

    const float* Aptr = A + (size_t)(bm + lrow) * K + lcol;
    const float* Bptr = B + (size_t)(bn + lrow) * K + lcol;

    float acc[8][8];
#pragma unroll
    for (int i = 0; i < 8; i++)
#pragma unroll
        for (int j = 0; j < 8; j++) acc[i][j] = 0.0f;

    for (int k0 = 0; k0 < K; k0 += 8) {
        float4 a4 = *(const float4*)(Aptr + k0);
        float4 b4 = *(const float4*)(Bptr + k0);
        As[lcol + 0][lrow] = a4.x; As[lcol + 1][lrow] = a4.y;
        As[lcol + 2][lrow] = a4.z; As[lcol + 3][lrow] = a4.w;
        Bs[lcol + 0][lrow] = b4.x; Bs[lcol + 1][lrow] = b4.y;
        Bs[lcol + 2][lrow] = b4.z; Bs[lcol + 3][lrow] = b4.w;
        __syncthreads();

#pragma unroll
        for (int kk = 0; kk < 8; kk++) {
            float af[8], bf[8];
            *(float4*)&af[0] = *(const float4*)&As[kk][ty * 8];
            *(float4*)&af[4] = *(const float4*)&As[kk][ty * 8 + 4];
            *(float4*)&bf[0] = *(const float4*)&Bs[kk][tx * 8];
            *(float4*)&bf[4] = *(const float4*)&Bs[kk][tx * 8 + 4];
#pragma unroll
            for (int i = 0; i < 8; i++)
#pragma unroll
                for (int j = 0; j < 8; j++)
                    acc[i][j] += af[i] * bf[j];
        }
        __syncthreads();
    }

#pragma unroll
    for (int i = 0; i < 8; i++) {
        const int m = bm + ty * 8 + i;
#pragma unroll
        for (int j4 = 0; j4 < 2; j4++) {
            const int n = bn + tx * 8 + j4 * 4;
            float4 o = make_float4(acc[i][j4 * 4 + 0], acc[i][j4 * 4 + 1],
                                   acc[i][j4 * 4 + 2], acc[i][j4 * 4 + 3]);
            size_t idx;
            if (MODE == 0) {
                const int b = m >> 11;       // m / SEQ
                const int s = m & 2047;      // m % SEQ
                const int h = n >> 6;        // n / dk
                const int dd = n & 63;       // n % dk
                idx = ((size_t)((b * NHEAD + h) * SEQ + s) << 6) + dd;
            } else {
                idx = (size_t)m * D_MODEL + n;
            }
            *(float4*)&C[idx] = o;
        }
    }
}

// ---------------------------------------------------------------------------
// Causal flash attention, fp32.
// grid = (S/64, B*H), 256 threads. 64 q-rows x 64 keys per tile, dk=64.
// Q/K in smem transposed [d][row] (pad 68 -> 4-way store conflicts only;
// compute-side loads are broadcast / single-row -> conflict-free).
// ---------------------------------------------------------------------------
#define QK_STRIDE 68

__global__ void __launch_bounds__(256) attn_kernel(
    const float* __restrict__ Q, const float* __restrict__ K,
    const float* __restrict__ V, float* __restrict__ O)
{
    extern __shared__ float sm[];
    float (*Qs)[QK_STRIDE] = (float(*)[QK_STRIDE])sm;                       // [64][68]
    float (*Ks)[QK_STRIDE] = (float(*)[QK_STRIDE])(sm + 64 * QK_STRIDE);    // [64][68]
    float (*Vs)[DKH]       = (float(*)[DKH])(sm + 2 * 64 * QK_STRIDE);      // [64][64]
    float (*Ps)[64]        = (float(*)[64])(sm + 2 * 64 * QK_STRIDE + 64 * DKH); // [64][64]

    const int tid = threadIdx.x;
    const int tx  = tid & 15;   // col group
    const int ty  = tid >> 4;   // row group
    const int bh  = blockIdx.y;
    const int qb  = blockIdx.x;
    const int q0  = qb * 64;

    const float* Qb = Q + (size_t)bh * SEQ * DKH;
    const float* Kb = K + (size_t)bh * SEQ * DKH;
    const float* Vb = V + (size_t)bh * SEQ * DKH;

    // Load Q tile (transposed store)
    for (int i = tid; i < 64 * 64; i += 256) {
        const int r = i >> 6, d = i & 63;
        Qs[d][r] = Qb[(size_t)(q0 + r) * DKH + d];
    }

    float m_i[4], l_i[4], acc[4][4];
#pragma unroll
    for (int i = 0; i < 4; i++) {
        m_i[i] = -1e30f;
        l_i[i] = 0.0f;
#pragma unroll
        for (int j = 0; j < 4; j++) acc[i][j] = 0.0f;
    }

    const int r0 = ty << 2;
    const int c0 = tx << 2;

    for (int jt = 0; jt <= qb; jt++) {
        const int k0 = jt * 64;
        __syncthreads();   // prior PV done before overwriting K/V
        for (int i = tid; i < 64 * 64; i += 256) {
            const int r = i >> 6, d = i & 63;
            const size_t gi = (size_t)(k0 + r) * DKH + d;
            Ks[d][r] = Kb[gi];
            Vs[r][d] = Vb[gi];
        }
        __syncthreads();

        // S = Q K^T (4x4 per thread)
        float s[4][4];
#pragma unroll
        for (int i = 0; i < 4; i++)
#pragma unroll
            for (int j = 0; j < 4; j++) s[i][j] = 0.0f;

#pragma unroll 16
        for (int d = 0; d < 64; d++) {
            float4 q4 = *(const float4*)&Qs[d][r0];
            float4 k4 = *(const float4*)&Ks[d][c0];
            float qr[4] = {q4.x, q4.y, q4.z, q4.w};
            float kc[4] = {k4.x, k4.y, k4.z, k4.w};
#pragma unroll
            for (int i = 0; i < 4; i++)
#pragma unroll
                for (int j = 0; j < 4; j++)
                    s[i][j] += qr[i] * kc[j];
        }

        // scale + causal mask (only diagonal tile needs masking)
        const bool diag = (jt == qb);
#pragma unroll
        for (int i = 0; i < 4; i++)
#pragma unroll
            for (int j = 0; j < 4; j++) {
                float v = s[i][j] * 0.125f;   // 1/sqrt(64)
                if (diag && (c0 + j) > (r0 + i)) v = -1e30f;
                s[i][j] = v;
            }

        // online softmax (row reductions across 16 tx lanes)
#pragma unroll
        for (int i = 0; i < 4; i++) {
            float rmax = fmaxf(fmaxf(s[i][0], s[i][1]), fmaxf(s[i][2], s[i][3]));
#pragma unroll
            for (int o = 8; o >= 1; o >>= 1)
                rmax = fmaxf(rmax, __shfl_xor_sync(0xffffffffu, rmax, o, 16));
            const float mnew = fmaxf(m_i[i], rmax);
            const float alpha = __expf(m_i[i] - mnew);
            m_i[i] = mnew;
            float rsum = 0.0f;
#pragma unroll
            for (int j = 0; j < 4; j++) {
                s[i][j] = __expf(s[i][j] - mnew);
                rsum += s[i][j];
            }
#pragma unroll
            for (int o = 8; o >= 1; o >>= 1)
                rsum += __shfl_xor_sync(0xffffffffu, rsum, o, 16);
            l_i[i] = l_i[i] * alpha + rsum;
#pragma unroll
            for (int j = 0; j < 4; j++) acc[i][j] *= alpha;
        }

        // stage P
#pragma unroll
        for (int i = 0; i < 4; i++)
#pragma unroll
            for (int j = 0; j < 4; j++)
                Ps[r0 + i][c0 + j] = s[i][j];
        __syncthreads();

        // O += P V
#pragma unroll 16
        for (int c = 0; c < 64; c++) {
            float4 v4 = *(const float4*)&Vs[c][c0];
            float vr[4] = {v4.x, v4.y, v4.z, v4.w};
            float p0 = Ps[r0 + 0][c];
            float p1 = Ps[r0 + 1][c];
            float p2 = Ps[r0 + 2][c];
            float p3 = Ps[r0 + 3][c];
#pragma unroll
            for (int j = 0; j < 4; j++) {
                acc[0][j] += p0 * vr[j];
                acc[1][j] += p1 * vr[j];
                acc[2][j] += p2 * vr[j];
                acc[3][j] += p3 * vr[j];
            }
        }
    }

    // write out: [B,S,D] with D = h*64 + d
    const int b = bh >> 4;
    const int h = bh & 15;
#pragma unroll
    for (int i = 0; i < 4; i++) {
        const float inv = 1.0f / l_i[i];
        const int srow = q0 + r0 + i;
        float* dst = O + ((size_t)(b * SEQ + srow) * D_MODEL) + h * DKH + c0;
        float4 o = make_float4(acc[i][0] * inv, acc[i][1] * inv,
                               acc[i][2] * inv, acc[i][3] * inv);
        *(float4*)dst = o;
    }
}

// ---------------------------------------------------------------------------
// launch
// ---------------------------------------------------------------------------
extern "C" void kernel_launch(void* const* d_in, const int* in_sizes, int n_in,
                              void* d_out, int out_size)
{
    (void)in_sizes; (void)n_in; (void)out_size;
    const float* x  = (const float*)d_in[0];
    const float* wq = (const float*)d_in[1];
    const float* wk = (const float*)d_in[2];
    const float* wv = (const float*)d_in[3];
    const float* wo = (const float*)d_in[4];
    float* out = (float*)d_out;

    float *q, *k, *v, *attn;
    cudaGetSymbolAddress((void**)&q, g_q);
    cudaGetSymbolAddress((void**)&k, g_k);
    cudaGetSymbolAddress((void**)&v, g_v);
    cudaGetSymbolAddress((void**)&attn, g_attn);

    const int attn_smem = (2 * 64 * QK_STRIDE + 2 * 64 * 64) * (int)sizeof(float); // 67584
    cudaFuncSetAttribute(attn_kernel, cudaFuncAttributeMaxDynamicSharedMemorySize,
                         attn_smem);

    dim3 ggrid(D_MODEL / 128, MTOK / 128);   // (8, 64)
    gemm_nt_kernel<0><<<ggrid, 256>>>(x, wq, q);
    gemm_nt_kernel<0><<<ggrid, 256>>>(x, wk, k);
    gemm_nt_kernel<0><<<ggrid, 256>>>(x, wv, v);

    attn_kernel<<<dim3(SEQ / 64, BATCH * NHEAD), 256, attn_smem>>>(q, k, v, attn);

    gemm_nt_kernel<1><<<ggrid, 256>>>(attn, wo, out);
}

// round 4
// speedup vs baseline: 1.6199x; 1.6199x over previous
#include <cuda_runtime.h>
#include <cuda_bf16.h>
#include <cstdint>
#include <math.h>

#define D_MODEL 1024
#define NHEAD 16
#define DKH 64
#define BATCH 4
#define SEQ 2048
#define MTOK (BATCH * SEQ)   // 8192

// ---------------------------------------------------------------------------
// Scratch (alloc-free rule: __device__ globals)
// ---------------------------------------------------------------------------
__device__ float g_q[MTOK * D_MODEL];      // [B,H,S,dk]
__device__ float g_k[MTOK * D_MODEL];
__device__ float g_v[MTOK * D_MODEL];
__device__ float g_attn[MTOK * D_MODEL];   // [B,S,D]

__device__ __nv_bfloat16 g_xh[MTOK * D_MODEL];
__device__ __nv_bfloat16 g_xl[MTOK * D_MODEL];
__device__ __nv_bfloat16 g_ah[MTOK * D_MODEL];
__device__ __nv_bfloat16 g_al[MTOK * D_MODEL];
__device__ __nv_bfloat16 g_wqh[D_MODEL * D_MODEL];
__device__ __nv_bfloat16 g_wql[D_MODEL * D_MODEL];
__device__ __nv_bfloat16 g_wkh[D_MODEL * D_MODEL];
__device__ __nv_bfloat16 g_wkl[D_MODEL * D_MODEL];
__device__ __nv_bfloat16 g_wvh[D_MODEL * D_MODEL];
__device__ __nv_bfloat16 g_wvl[D_MODEL * D_MODEL];
__device__ __nv_bfloat16 g_woh[D_MODEL * D_MODEL];
__device__ __nv_bfloat16 g_wol[D_MODEL * D_MODEL];

// ---------------------------------------------------------------------------
// helpers (arch-portable only: cp.async / ldmatrix / mma.sync)
// ---------------------------------------------------------------------------
__device__ __forceinline__ uint32_t smem_u32(const void* p) {
    uint32_t a;
    asm("{ .reg .u64 t; cvta.to.shared.u64 t, %1; cvt.u32.u64 %0, t; }"
        : "=r"(a) : "l"(p));
    return a;
}

#define LDMATRIX_X4(r0, r1, r2, r3, addr) \
    asm volatile("ldmatrix.sync.aligned.m8n8.x4.shared.b16 {%0,%1,%2,%3}, [%4];" \
        : "=r"(r0), "=r"(r1), "=r"(r2), "=r"(r3) : "r"(addr))

#define MMA16816(d, a0, a1, a2, a3, b0, b1) \
    asm volatile("mma.sync.aligned.m16n8k16.row.col.f32.bf16.bf16.f32 " \
        "{%0,%1,%2,%3}, {%4,%5,%6,%7}, {%8,%9}, {%0,%1,%2,%3};" \
        : "+f"((d)[0]), "+f"((d)[1]), "+f"((d)[2]), "+f"((d)[3]) \
        : "r"(a0), "r"(a1), "r"(a2), "r"(a3), "r"(b0), "r"(b1))

#define CP_ASYNC16(saddr, gaddr) \
    asm volatile("cp.async.cg.shared.global [%0], [%1], 16;" \
        :: "r"(saddr), "l"(gaddr))
#define CP_COMMIT() asm volatile("cp.async.commit_group;" ::: "memory")
#define CP_WAIT(n)  asm volatile("cp.async.wait_group %0;" :: "n"(n) : "memory")

// ---------------------------------------------------------------------------
// fp32 -> bf16 hi/lo split
// ---------------------------------------------------------------------------
__global__ void __launch_bounds__(256) split_kernel(
    const float* __restrict__ in,
    __nv_bfloat16* __restrict__ hi, __nv_bfloat16* __restrict__ lo, int n4)
{
    int i = blockIdx.x * 256 + threadIdx.x;
    if (i >= n4) return;
    float4 v = ((const float4*)in)[i];
    float f[4] = {v.x, v.y, v.z, v.w};
    __nv_bfloat162 h01, h23, l01, l23;
    __nv_bfloat16 h0 = __float2bfloat16(f[0]);
    __nv_bfloat16 h1 = __float2bfloat16(f[1]);
    __nv_bfloat16 h2 = __float2bfloat16(f[2]);
    __nv_bfloat16 h3 = __float2bfloat16(f[3]);
    h01.x = h0; h01.y = h1; h23.x = h2; h23.y = h3;
    l01.x = __float2bfloat16(f[0] - __bfloat162float(h0));
    l01.y = __float2bfloat16(f[1] - __bfloat162float(h1));
    l23.x = __float2bfloat16(f[2] - __bfloat162float(h2));
    l23.y = __float2bfloat16(f[3] - __bfloat162float(h3));
    ((__nv_bfloat162*)hi)[2 * i]     = h01;
    ((__nv_bfloat162*)hi)[2 * i + 1] = h23;
    ((__nv_bfloat162*)lo)[2 * i]     = l01;
    ((__nv_bfloat162*)lo)[2 * i + 1] = l23;
}

// ---------------------------------------------------------------------------
// mma.sync bf16-split GEMM: C[m,n] = sum_k A[m,k]*B[n,k]  (fp32-equivalent)
// 128x128 tile/CTA, BK=32, 3-stage cp.async pipeline.
// smem tiles [128][40] bf16 (80B row stride -> conflict-free ldmatrix).
// MODE 0: write head-split [B,H,S,dk]; MODE 1: plain [M, D_MODEL].
// ---------------------------------------------------------------------------
#define BM 128
#define BN 128
#define BK 32
#define CHUNKS (D_MODEL / BK)             // 32
#define TPAD 40                            // bf16 elements per row in smem
#define TILE_B (128 * TPAD * 2)            // 10240 bytes per tile
#define STAGE_B (4 * TILE_B)               // 40960 (Ah,Al,Bh,Bl)
#define GEMM_SMEM (3 * STAGE_B)            // 122880

template <int MODE>
__global__ void __launch_bounds__(256) gemm_bf16_kernel(
    const __nv_bfloat16* __restrict__ Ah, const __nv_bfloat16* __restrict__ Al,
    const __nv_bfloat16* __restrict__ Bh, const __nv_bfloat16* __restrict__ Bl,
    float* __restrict__ C)
{
    extern __shared__ __align__(128) char smem[];
    const uint32_t sbase = smem_u32(smem);
    const int tid  = threadIdx.x;
    const int wid  = tid >> 5;
    const int lane = tid & 31;
    const int bm = blockIdx.y * BM;
    const int bn = blockIdx.x * BN;
    const int K = D_MODEL;

    const int warp_m = wid >> 2;   // 0..1  (64 rows each)
    const int warp_n = wid & 3;    // 0..3  (32 cols each)

    // stage loader: 4 tiles x (128 rows x 2 sixteen-byte cols... actually 4)
    auto load_stage = [&](int chunk, int s) {
        const uint32_t st = sbase + s * STAGE_B;
        const int k0 = chunk * BK;
#pragma unroll
        for (int u = 0; u < 8; u++) {
            const int id = u * 256 + tid;      // 0..2047
            const int t = id >> 9;             // 0:Ah 1:Al 2:Bh 3:Bl
            const int idx = id & 511;
            const int row = idx >> 2;          // 0..127
            const int c = idx & 3;             // 16B col
            const __nv_bfloat16* g;
            int grow;
            if (t == 0)      { g = Ah; grow = bm + row; }
            else if (t == 1) { g = Al; grow = bm + row; }
            else if (t == 2) { g = Bh; grow = bn + row; }
            else             { g = Bl; grow = bn + row; }
            const __nv_bfloat16* gaddr = g + (size_t)grow * K + k0 + c * 8;
            const uint32_t saddr = st + t * TILE_B + row * (TPAD * 2) + c * 16;
            CP_ASYNC16(saddr, gaddr);
        }
        CP_COMMIT();
    };

    load_stage(0, 0);
    load_stage(1, 1);
    load_stage(2, 2);

    float acc[4][4][4];
#pragma unroll
    for (int i = 0; i < 4; i++)
#pragma unroll
        for (int j = 0; j < 4; j++)
#pragma unroll
            for (int r = 0; r < 4; r++) acc[i][j][r] = 0.0f;

    // ldmatrix base addresses (row part varies by lane)
    const int a_row = warp_m * 64 + (lane & 15);
    const uint32_t a_off = a_row * (TPAD * 2) + (lane >> 4) * 16;
    const int b_row = warp_n * 32 + ((lane >> 4) & 1) * 8 + (lane & 7);
    const uint32_t b_off = b_row * (TPAD * 2) + ((lane >> 3) & 1) * 16;

    for (int chunk = 0; chunk < CHUNKS; chunk++) {
        const int s = chunk - (chunk / 3) * 3;
        CP_WAIT(2);
        __syncthreads();
        const uint32_t st = sbase + s * STAGE_B;
        const uint32_t aH = st + a_off;
        const uint32_t aL = st + TILE_B + a_off;
        const uint32_t bH = st + 2 * TILE_B + b_off;
        const uint32_t bL = st + 3 * TILE_B + b_off;

#pragma unroll
        for (int ks = 0; ks < 2; ks++) {
            const uint32_t kb = ks * 32;   // 16 bf16 = 32 bytes
            uint32_t fAH[4][4], fAL[4][4], fBH[4][2], fBL[4][2];
#pragma unroll
            for (int mt = 0; mt < 4; mt++) {
                LDMATRIX_X4(fAH[mt][0], fAH[mt][1], fAH[mt][2], fAH[mt][3],
                            aH + mt * 16 * (TPAD * 2) + kb);
                LDMATRIX_X4(fAL[mt][0], fAL[mt][1], fAL[mt][2], fAL[mt][3],
                            aL + mt * 16 * (TPAD * 2) + kb);
            }
#pragma unroll
            for (int np = 0; np < 2; np++) {
                LDMATRIX_X4(fBH[2 * np][0], fBH[2 * np][1],
                            fBH[2 * np + 1][0], fBH[2 * np + 1][1],
                            bH + np * 16 * (TPAD * 2) + kb);
                LDMATRIX_X4(fBL[2 * np][0], fBL[2 * np][1],
                            fBL[2 * np + 1][0], fBL[2 * np + 1][1],
                            bL + np * 16 * (TPAD * 2) + kb);
            }
#pragma unroll
            for (int mt = 0; mt < 4; mt++)
#pragma unroll
                for (int nt = 0; nt < 4; nt++) {
                    MMA16816(acc[mt][nt], fAH[mt][0], fAH[mt][1], fAH[mt][2],
                             fAH[mt][3], fBH[nt][0], fBH[nt][1]);
                    MMA16816(acc[mt][nt], fAH[mt][0], fAH[mt][1], fAH[mt][2],
                             fAH[mt][3], fBL[nt][0], fBL[nt][1]);
                    MMA16816(acc[mt][nt], fAL[mt][0], fAL[mt][1], fAL[mt][2],
                             fAL[mt][3], fBH[nt][0], fBH[nt][1]);
                }
        }
        __syncthreads();
        if (chunk + 3 < CHUNKS) load_stage(chunk + 3, s);
    }

    // epilogue: registers -> gmem (float2 stores)
#pragma unroll
    for (int mt = 0; mt < 4; mt++) {
#pragma unroll
        for (int half = 0; half < 2; half++) {
            const int m = bm + warp_m * 64 + mt * 16 + (lane >> 2) + half * 8;
#pragma unroll
            for (int nt = 0; nt < 4; nt++) {
                const int n = bn + warp_n * 32 + nt * 8 + (lane & 3) * 2;
                float2 o = make_float2(acc[mt][nt][2 * half],
                                       acc[mt][nt][2 * half + 1]);
                size_t idx;
                if (MODE == 0) {
                    const int b = m >> 11;
                    const int sq = m & 2047;
                    const int h = n >> 6;
                    const int dd = n & 63;
                    idx = ((size_t)((b * NHEAD + h) * SEQ + sq) << 6) + dd;
                } else {
                    idx = (size_t)m * D_MODEL + n;
                }
                *(float2*)&C[idx] = o;
            }
        }
    }
}

// ---------------------------------------------------------------------------
// Causal flash attention, fp32 (unchanged from round 1)
// ---------------------------------------------------------------------------
#define QK_STRIDE 68

__global__ void __launch_bounds__(256) attn_kernel(
    const float* __restrict__ Q, const float* __restrict__ K,
    const float* __restrict__ V, float* __restrict__ O)
{
    extern __shared__ float sm[];
    float (*Qs)[QK_STRIDE] = (float(*)[QK_STRIDE])sm;
    float (*Ks)[QK_STRIDE] = (float(*)[QK_STRIDE])(sm + 64 * QK_STRIDE);
    float (*Vs)[DKH]       = (float(*)[DKH])(sm + 2 * 64 * QK_STRIDE);
    float (*Ps)[64]        = (float(*)[64])(sm + 2 * 64 * QK_STRIDE + 64 * DKH);

    const int tid = threadIdx.x;
    const int tx  = tid & 15;
    const int ty  = tid >> 4;
    const int bh  = blockIdx.y;
    const int qb  = blockIdx.x;
    const int q0  = qb * 64;

    const float* Qb = Q + (size_t)bh * SEQ * DKH;
    const float* Kb = K + (size_t)bh * SEQ * DKH;
    const float* Vb = V + (size_t)bh * SEQ * DKH;

    for (int i = tid; i < 64 * 64; i += 256) {
        const int r = i >> 6, d = i & 63;
        Qs[d][r] = Qb[(size_t)(q0 + r) * DKH + d];
    }

    float m_i[4], l_i[4], acc[4][4];
#pragma unroll
    for (int i = 0; i < 4; i++) {
        m_i[i] = -1e30f;
        l_i[i] = 0.0f;
#pragma unroll
        for (int j = 0; j < 4; j++) acc[i][j] = 0.0f;
    }

    const int r0 = ty << 2;
    const int c0 = tx << 2;

    for (int jt = 0; jt <= qb; jt++) {
        const int k0 = jt * 64;
        __syncthreads();
        for (int i = tid; i < 64 * 64; i += 256) {
            const int r = i >> 6, d = i & 63;
            const size_t gi = (size_t)(k0 + r) * DKH + d;
            Ks[d][r] = Kb[gi];
            Vs[r][d] = Vb[gi];
        }
        __syncthreads();

        float s[4][4];
#pragma unroll
        for (int i = 0; i < 4; i++)
#pragma unroll
            for (int j = 0; j < 4; j++) s[i][j] = 0.0f;

#pragma unroll 16
        for (int d = 0; d < 64; d++) {
            float4 q4 = *(const float4*)&Qs[d][r0];
            float4 k4 = *(const float4*)&Ks[d][c0];
            float qr[4] = {q4.x, q4.y, q4.z, q4.w};
            float kc[4] = {k4.x, k4.y, k4.z, k4.w};
#pragma unroll
            for (int i = 0; i < 4; i++)
#pragma unroll
                for (int j = 0; j < 4; j++)
                    s[i][j] += qr[i] * kc[j];
        }

        const bool diag = (jt == qb);
#pragma unroll
        for (int i = 0; i < 4; i++)
#pragma unroll
            for (int j = 0; j < 4; j++) {
                float v = s[i][j] * 0.125f;
                if (diag && (c0 + j) > (r0 + i)) v = -1e30f;
                s[i][j] = v;
            }

#pragma unroll
        for (int i = 0; i < 4; i++) {
            float rmax = fmaxf(fmaxf(s[i][0], s[i][1]), fmaxf(s[i][2], s[i][3]));
#pragma unroll
            for (int o = 8; o >= 1; o >>= 1)
                rmax = fmaxf(rmax, __shfl_xor_sync(0xffffffffu, rmax, o, 16));
            const float mnew = fmaxf(m_i[i], rmax);
            const float alpha = __expf(m_i[i] - mnew);
            m_i[i] = mnew;
            float rsum = 0.0f;
#pragma unroll
            for (int j = 0; j < 4; j++) {
                s[i][j] = __expf(s[i][j] - mnew);
                rsum += s[i][j];
            }
#pragma unroll
            for (int o = 8; o >= 1; o >>= 1)
                rsum += __shfl_xor_sync(0xffffffffu, rsum, o, 16);
            l_i[i] = l_i[i] * alpha + rsum;
#pragma unroll
            for (int j = 0; j < 4; j++) acc[i][j] *= alpha;
        }

#pragma unroll
        for (int i = 0; i < 4; i++)
#pragma unroll
            for (int j = 0; j < 4; j++)
                Ps[r0 + i][c0 + j] = s[i][j];
        __syncthreads();

#pragma unroll 16
        for (int c = 0; c < 64; c++) {
            float4 v4 = *(const float4*)&Vs[c][c0];
            float vr[4] = {v4.x, v4.y, v4.z, v4.w};
            float p0 = Ps[r0 + 0][c];
            float p1 = Ps[r0 + 1][c];
            float p2 = Ps[r0 + 2][c];
            float p3 = Ps[r0 + 3][c];
#pragma unroll
            for (int j = 0; j < 4; j++) {
                acc[0][j] += p0 * vr[j];
                acc[1][j] += p1 * vr[j];
                acc[2][j] += p2 * vr[j];
                acc[3][j] += p3 * vr[j];
            }
        }
    }

    const int b = bh >> 4;
    const int h = bh & 15;
#pragma unroll
    for (int i = 0; i < 4; i++) {
        const float inv = 1.0f / l_i[i];
        const int srow = q0 + r0 + i;
        float* dst = O + ((size_t)(b * SEQ + srow) * D_MODEL) + h * DKH + c0;
        float4 o = make_float4(acc[i][0] * inv, acc[i][1] * inv,
                               acc[i][2] * inv, acc[i][3] * inv);
        *(float4*)dst = o;
    }
}

// ---------------------------------------------------------------------------
// launch
// ---------------------------------------------------------------------------
extern "C" void kernel_launch(void* const* d_in, const int* in_sizes, int n_in,
                              void* d_out, int out_size)
{
    (void)in_sizes; (void)n_in; (void)out_size;
    const float* x  = (const float*)d_in[0];
    const float* wq = (const float*)d_in[1];
    const float* wk = (const float*)d_in[2];
    const float* wv = (const float*)d_in[3];
    const float* wo = (const float*)d_in[4];
    float* out = (float*)d_out;

    float *q, *k, *v, *attn;
    cudaGetSymbolAddress((void**)&q, g_q);
    cudaGetSymbolAddress((void**)&k, g_k);
    cudaGetSymbolAddress((void**)&v, g_v);
    cudaGetSymbolAddress((void**)&attn, g_attn);
    __nv_bfloat16 *xh, *xl, *ah, *al;
    __nv_bfloat16 *wqh, *wql, *wkh, *wkl, *wvh, *wvl, *woh, *wol;
    cudaGetSymbolAddress((void**)&xh, g_xh);
    cudaGetSymbolAddress((void**)&xl, g_xl);
    cudaGetSymbolAddress((void**)&ah, g_ah);
    cudaGetSymbolAddress((void**)&al, g_al);
    cudaGetSymbolAddress((void**)&wqh, g_wqh);
    cudaGetSymbolAddress((void**)&wql, g_wql);
    cudaGetSymbolAddress((void**)&wkh, g_wkh);
    cudaGetSymbolAddress((void**)&wkl, g_wkl);
    cudaGetSymbolAddress((void**)&wvh, g_wvh);
    cudaGetSymbolAddress((void**)&wvl, g_wvl);
    cudaGetSymbolAddress((void**)&woh, g_woh);
    cudaGetSymbolAddress((void**)&wol, g_wol);

    const int attn_smem = (2 * 64 * QK_STRIDE + 2 * 64 * 64) * (int)sizeof(float);
    cudaFuncSetAttribute(attn_kernel, cudaFuncAttributeMaxDynamicSharedMemorySize,
                         attn_smem);
    cudaFuncSetAttribute(gemm_bf16_kernel<0>,
                         cudaFuncAttributeMaxDynamicSharedMemorySize, GEMM_SMEM);
    cudaFuncSetAttribute(gemm_bf16_kernel<1>,
                         cudaFuncAttributeMaxDynamicSharedMemorySize, GEMM_SMEM);

    const int nx4 = MTOK * D_MODEL / 4;
    const int nw4 = D_MODEL * D_MODEL / 4;
    split_kernel<<<(nx4 + 255) / 256, 256>>>(x, xh, xl, nx4);
    split_kernel<<<(nw4 + 255) / 256, 256>>>(wq, wqh, wql, nw4);
    split_kernel<<<(nw4 + 255) / 256, 256>>>(wk, wkh, wkl, nw4);
    split_kernel<<<(nw4 + 255) / 256, 256>>>(wv, wvh, wvl, nw4);
    split_kernel<<<(nw4 + 255) / 256, 256>>>(wo, woh, wol, nw4);

    dim3 ggrid(D_MODEL / BN, MTOK / BM);   // (8, 64)
    gemm_bf16_kernel<0><<<ggrid, 256, GEMM_SMEM>>>(xh, xl, wqh, wql, q);
    gemm_bf16_kernel<0><<<ggrid, 256, GEMM_SMEM>>>(xh, xl, wkh, wkl, k);
    gemm_bf16_kernel<0><<<ggrid, 256, GEMM_SMEM>>>(xh, xl, wvh, wvl, v);

    attn_kernel<<<dim3(SEQ / 64, BATCH * NHEAD), 256, attn_smem>>>(q, k, v, attn);

    split_kernel<<<(nx4 + 255) / 256, 256>>>(attn, ah, al, nx4);
    gemm_bf16_kernel<1><<<ggrid, 256, GEMM_SMEM>>>(ah, al, woh, wol, out);
}

// round 5
// speedup vs baseline: 2.6955x; 1.6641x over previous
#include <cuda_runtime.h>
#include <cuda_bf16.h>
#include <cstdint>
#include <math.h>

#define D_MODEL 1024
#define NHEAD 16
#define DKH 64
#define BATCH 4
#define SEQ 2048
#define MTOK (BATCH * SEQ)   // 8192

// ---------------------------------------------------------------------------
// Scratch (alloc-free rule: __device__ globals)
// ---------------------------------------------------------------------------
__device__ __nv_bfloat16 g_xh[MTOK * D_MODEL];
__device__ __nv_bfloat16 g_xl[MTOK * D_MODEL];
__device__ __nv_bfloat16 g_qh[MTOK * D_MODEL];   // [B,H,S,64]
__device__ __nv_bfloat16 g_ql[MTOK * D_MODEL];
__device__ __nv_bfloat16 g_kh[MTOK * D_MODEL];
__device__ __nv_bfloat16 g_kl[MTOK * D_MODEL];
__device__ __nv_bfloat16 g_vh[MTOK * D_MODEL];
__device__ __nv_bfloat16 g_vl[MTOK * D_MODEL];
__device__ __nv_bfloat16 g_ah[MTOK * D_MODEL];   // attn out [B,S,D]
__device__ __nv_bfloat16 g_al[MTOK * D_MODEL];
__device__ __nv_bfloat16 g_wqh[D_MODEL * D_MODEL];
__device__ __nv_bfloat16 g_wql[D_MODEL * D_MODEL];
__device__ __nv_bfloat16 g_wkh[D_MODEL * D_MODEL];
__device__ __nv_bfloat16 g_wkl[D_MODEL * D_MODEL];
__device__ __nv_bfloat16 g_wvh[D_MODEL * D_MODEL];
__device__ __nv_bfloat16 g_wvl[D_MODEL * D_MODEL];
__device__ __nv_bfloat16 g_woh[D_MODEL * D_MODEL];
__device__ __nv_bfloat16 g_wol[D_MODEL * D_MODEL];

// ---------------------------------------------------------------------------
// helpers (arch-portable only: cp.async / ldmatrix / mma.sync)
// ---------------------------------------------------------------------------
__device__ __forceinline__ uint32_t smem_u32(const void* p) {
    uint32_t a;
    asm("{ .reg .u64 t; cvta.to.shared.u64 t, %1; cvt.u32.u64 %0, t; }"
        : "=r"(a) : "l"(p));
    return a;
}

#define LDMATRIX_X4(r0, r1, r2, r3, addr) \
    asm volatile("ldmatrix.sync.aligned.m8n8.x4.shared.b16 {%0,%1,%2,%3}, [%4];" \
        : "=r"(r0), "=r"(r1), "=r"(r2), "=r"(r3) : "r"(addr))

#define LDMATRIX_X4_T(r0, r1, r2, r3, addr) \
    asm volatile("ldmatrix.sync.aligned.m8n8.x4.trans.shared.b16 {%0,%1,%2,%3}, [%4];" \
        : "=r"(r0), "=r"(r1), "=r"(r2), "=r"(r3) : "r"(addr))

#define MMA16816(d, a0, a1, a2, a3, b0, b1) \
    asm volatile("mma.sync.aligned.m16n8k16.row.col.f32.bf16.bf16.f32 " \
        "{%0,%1,%2,%3}, {%4,%5,%6,%7}, {%8,%9}, {%0,%1,%2,%3};" \
        : "+f"((d)[0]), "+f"((d)[1]), "+f"((d)[2]), "+f"((d)[3]) \
        : "r"(a0), "r"(a1), "r"(a2), "r"(a3), "r"(b0), "r"(b1))

#define CP_ASYNC16(saddr, gaddr) \
    asm volatile("cp.async.cg.shared.global [%0], [%1], 16;" \
        :: "r"(saddr), "l"(gaddr))
#define CP_COMMIT() asm volatile("cp.async.commit_group;" ::: "memory")
#define CP_WAIT(n)  asm volatile("cp.async.wait_group %0;" :: "n"(n) : "memory")

// pack two f32 -> bf16x2 reg (lo in low half, hi in high half)
#define PACK_BF16X2(r, lo, hi) \
    asm("cvt.rn.bf16x2.f32 %0, %1, %2;" : "=r"(r) : "f"(hi), "f"(lo))

// split two f32 into bf16x2 hi-reg + bf16x2 residual-reg
__device__ __forceinline__ void split2(float v0, float v1,
                                       uint32_t& ph, uint32_t& pl) {
    PACK_BF16X2(ph, v0, v1);
    const float f0 = __uint_as_float(ph << 16);
    const float f1 = __uint_as_float(ph & 0xffff0000u);
    PACK_BF16X2(pl, v0 - f0, v1 - f1);
}

// ---------------------------------------------------------------------------
// fp32 -> bf16 hi/lo split (inputs x + weights only)
// ---------------------------------------------------------------------------
__global__ void __launch_bounds__(256) split_kernel(
    const float* __restrict__ in,
    __nv_bfloat16* __restrict__ hi, __nv_bfloat16* __restrict__ lo, int n4)
{
    int i = blockIdx.x * 256 + threadIdx.x;
    if (i >= n4) return;
    float4 v = ((const float4*)in)[i];
    uint32_t h01, l01, h23, l23;
    split2(v.x, v.y, h01, l01);
    split2(v.z, v.w, h23, l23);
    ((uint32_t*)hi)[2 * i]     = h01;
    ((uint32_t*)hi)[2 * i + 1] = h23;
    ((uint32_t*)lo)[2 * i]     = l01;
    ((uint32_t*)lo)[2 * i + 1] = l23;
}

// ---------------------------------------------------------------------------
// mma.sync bf16-split GEMM: C[m,n] = sum_k A[m,k]*B[n,k]
// MODE 0: write bf16 hi/lo head-split [B,H,S,dk]; MODE 1: fp32 [M, D_MODEL].
// ---------------------------------------------------------------------------
#define BM 128
#define BN 128
#define BK 32
#define CHUNKS (D_MODEL / BK)
#define TPAD 40
#define TILE_B (128 * TPAD * 2)
#define STAGE_B (4 * TILE_B)
#define GEMM_SMEM (3 * STAGE_B)

template <int MODE>
__global__ void __launch_bounds__(256) gemm_bf16_kernel(
    const __nv_bfloat16* __restrict__ Ah, const __nv_bfloat16* __restrict__ Al,
    const __nv_bfloat16* __restrict__ Bh, const __nv_bfloat16* __restrict__ Bl,
    __nv_bfloat16* __restrict__ Ch, __nv_bfloat16* __restrict__ Cl,
    float* __restrict__ Cf)
{
    extern __shared__ __align__(128) char smem[];
    const uint32_t sbase = smem_u32(smem);
    const int tid  = threadIdx.x;
    const int wid  = tid >> 5;
    const int lane = tid & 31;
    const int bm = blockIdx.y * BM;
    const int bn = blockIdx.x * BN;
    const int K = D_MODEL;

    const int warp_m = wid >> 2;
    const int warp_n = wid & 3;

    auto load_stage = [&](int chunk, int s) {
        const uint32_t st = sbase + s * STAGE_B;
        const int k0 = chunk * BK;
#pragma unroll
        for (int u = 0; u < 8; u++) {
            const int id = u * 256 + tid;
            const int t = id >> 9;
            const int idx = id & 511;
            const int row = idx >> 2;
            const int c = idx & 3;
            const __nv_bfloat16* g;
            int grow;
            if (t == 0)      { g = Ah; grow = bm + row; }
            else if (t == 1) { g = Al; grow = bm + row; }
            else if (t == 2) { g = Bh; grow = bn + row; }
            else             { g = Bl; grow = bn + row; }
            const __nv_bfloat16* gaddr = g + (size_t)grow * K + k0 + c * 8;
            const uint32_t saddr = st + t * TILE_B + row * (TPAD * 2) + c * 16;
            CP_ASYNC16(saddr, gaddr);
        }
        CP_COMMIT();
    };

    load_stage(0, 0);
    load_stage(1, 1);
    load_stage(2, 2);

    float acc[4][4][4];
#pragma unroll
    for (int i = 0; i < 4; i++)
#pragma unroll
        for (int j = 0; j < 4; j++)
#pragma unroll
            for (int r = 0; r < 4; r++) acc[i][j][r] = 0.0f;

    const int a_row = warp_m * 64 + (lane & 15);
    const uint32_t a_off = a_row * (TPAD * 2) + (lane >> 4) * 16;
    const int b_row = warp_n * 32 + ((lane >> 4) & 1) * 8 + (lane & 7);
    const uint32_t b_off = b_row * (TPAD * 2) + ((lane >> 3) & 1) * 16;

    for (int chunk = 0; chunk < CHUNKS; chunk++) {
        const int s = chunk - (chunk / 3) * 3;
        CP_WAIT(2);
        __syncthreads();
        const uint32_t st = sbase + s * STAGE_B;
        const uint32_t aH = st + a_off;
        const uint32_t aL = st + TILE_B + a_off;
        const uint32_t bH = st + 2 * TILE_B + b_off;
        const uint32_t bL = st + 3 * TILE_B + b_off;

#pragma unroll
        for (int ks = 0; ks < 2; ks++) {
            const uint32_t kb = ks * 32;
            uint32_t fAH[4][4], fAL[4][4], fBH[4][2], fBL[4][2];
#pragma unroll
            for (int mt = 0; mt < 4; mt++) {
                LDMATRIX_X4(fAH[mt][0], fAH[mt][1], fAH[mt][2], fAH[mt][3],
                            aH + mt * 16 * (TPAD * 2) + kb);
                LDMATRIX_X4(fAL[mt][0], fAL[mt][1], fAL[mt][2], fAL[mt][3],
                            aL + mt * 16 * (TPAD * 2) + kb);
            }
#pragma unroll
            for (int np = 0; np < 2; np++) {
                LDMATRIX_X4(fBH[2 * np][0], fBH[2 * np][1],
                            fBH[2 * np + 1][0], fBH[2 * np + 1][1],
                            bH + np * 16 * (TPAD * 2) + kb);
                LDMATRIX_X4(fBL[2 * np][0], fBL[2 * np][1],
                            fBL[2 * np + 1][0], fBL[2 * np + 1][1],
                            bL + np * 16 * (TPAD * 2) + kb);
            }
#pragma unroll
            for (int mt = 0; mt < 4; mt++)
#pragma unroll
                for (int nt = 0; nt < 4; nt++) {
                    MMA16816(acc[mt][nt], fAH[mt][0], fAH[mt][1], fAH[mt][2],
                             fAH[mt][3], fBH[nt][0], fBH[nt][1]);
                    MMA16816(acc[mt][nt], fAH[mt][0], fAH[mt][1], fAH[mt][2],
                             fAH[mt][3], fBL[nt][0], fBL[nt][1]);
                    MMA16816(acc[mt][nt], fAL[mt][0], fAL[mt][1], fAL[mt][2],
                             fAL[mt][3], fBH[nt][0], fBH[nt][1]);
                }
        }
        __syncthreads();
        if (chunk + 3 < CHUNKS) load_stage(chunk + 3, s);
    }

#pragma unroll
    for (int mt = 0; mt < 4; mt++) {
#pragma unroll
        for (int half = 0; half < 2; half++) {
            const int m = bm + warp_m * 64 + mt * 16 + (lane >> 2) + half * 8;
#pragma unroll
            for (int nt = 0; nt < 4; nt++) {
                const int n = bn + warp_n * 32 + nt * 8 + (lane & 3) * 2;
                const float v0 = acc[mt][nt][2 * half];
                const float v1 = acc[mt][nt][2 * half + 1];
                if (MODE == 0) {
                    const int b = m >> 11;
                    const int sq = m & 2047;
                    const int h = n >> 6;
                    const int dd = n & 63;
                    const size_t idx =
                        ((size_t)((b * NHEAD + h) * SEQ + sq) << 6) + dd;
                    uint32_t ph, pl;
                    split2(v0, v1, ph, pl);
                    *(uint32_t*)&Ch[idx] = ph;
                    *(uint32_t*)&Cl[idx] = pl;
                } else {
                    const size_t idx = (size_t)m * D_MODEL + n;
                    *(float2*)&Cf[idx] = make_float2(v0, v1);
                }
            }
        }
    }
}

// ---------------------------------------------------------------------------
// Tensor-core causal flash attention (bf16 hi/lo split, fp32 accum).
// CTA: 128 q-rows, 8 warps (16 rows each). Key tiles of 64, dk=64.
// Writes bf16 hi/lo attn output [B,S,D] for the output GEMM.
// ---------------------------------------------------------------------------
#define ATPAD 72
#define AT_STRIDE (ATPAD * 2)          // 144 bytes/row
#define AT_TILE_B (64 * AT_STRIDE)     // 9216
#define AT_STAGE_B (4 * AT_TILE_B)     // 36864 (Kh,Kl,Vh,Vl)
#define ATTN_SMEM (2 * AT_STAGE_B)     // 73728

__global__ void __launch_bounds__(256) attn_mma_kernel(
    const __nv_bfloat16* __restrict__ Qh, const __nv_bfloat16* __restrict__ Ql,
    const __nv_bfloat16* __restrict__ Kh, const __nv_bfloat16* __restrict__ Kl,
    const __nv_bfloat16* __restrict__ Vh, const __nv_bfloat16* __restrict__ Vl,
    __nv_bfloat16* __restrict__ Ah, __nv_bfloat16* __restrict__ Al)
{
    extern __shared__ __align__(128) char smem[];
    const uint32_t sbase = smem_u32(smem);
    const int tid  = threadIdx.x;
    const int wid  = tid >> 5;
    const int lane = tid & 31;
    const int bh = blockIdx.y;
    const int qb = blockIdx.x;
    const int q0 = qb * 128;
    const size_t base_off = (size_t)bh * SEQ * DKH;

    // ---- load Q tile (128x64 hi/lo) into stage-0 smem, then to registers
#pragma unroll
    for (int u = 0; u < 8; u++) {
        const int id = u * 256 + tid;      // 0..2047
        const int t = id >> 10;            // 0 hi, 1 lo
        const int idx = id & 1023;
        const int row = idx >> 3;
        const int c = idx & 7;
        const __nv_bfloat16* g = t ? Ql : Qh;
        CP_ASYNC16(sbase + t * (128 * AT_STRIDE) + row * AT_STRIDE + c * 16,
                   g + base_off + (size_t)(q0 + row) * DKH + c * 8);
    }
    CP_COMMIT();
    CP_WAIT(0);
    __syncthreads();

    uint32_t Qh_[4][4], Ql_[4][4];
    {
        const uint32_t qa =
            sbase + (16 * wid + (lane & 15)) * AT_STRIDE + (lane >> 4) * 16;
#pragma unroll
        for (int ks = 0; ks < 4; ks++) {
            LDMATRIX_X4(Qh_[ks][0], Qh_[ks][1], Qh_[ks][2], Qh_[ks][3],
                        qa + ks * 32);
            LDMATRIX_X4(Ql_[ks][0], Ql_[ks][1], Ql_[ks][2], Ql_[ks][3],
                        qa + 128 * AT_STRIDE + ks * 32);
        }
    }
    __syncthreads();   // Q consumed; stage 0 reusable

    auto load_kv = [&](int jt, int buf) {
        const uint32_t st = sbase + buf * AT_STAGE_B;
        const int k0 = jt * 64;
#pragma unroll
        for (int u = 0; u < 8; u++) {
            const int id = u * 256 + tid;
            const int t = id >> 9;         // 0:Kh 1:Kl 2:Vh 3:Vl
            const int idx = id & 511;
            const int row = idx >> 3;
            const int c = idx & 7;
            const __nv_bfloat16* g = (t == 0) ? Kh : (t == 1) ? Kl
                                     : (t == 2) ? Vh : Vl;
            CP_ASYNC16(st + t * AT_TILE_B + row * AT_STRIDE + c * 16,
                       g + base_off + (size_t)(k0 + row) * DKH + c * 8);
        }
        CP_COMMIT();
    };

    float O_[8][4];
#pragma unroll
    for (int i = 0; i < 8; i++)
#pragma unroll
        for (int j = 0; j < 4; j++) O_[i][j] = 0.0f;
    float m_lo = -1e30f, m_hi = -1e30f, l_lo = 0.0f, l_hi = 0.0f;

    const int row_lo = q0 + 16 * wid + (lane >> 2);
    const int row_hi = row_lo + 8;
    const uint32_t b_off =
        (((lane >> 4) & 1) * 8 + (lane & 7)) * AT_STRIDE + ((lane >> 3) & 1) * 16;
    const uint32_t v_off = (lane & 15) * AT_STRIDE + (lane >> 4) * 16;

    const int jmax = 2 * qb + 1;
    load_kv(0, 0);

    for (int jt = 0; jt <= jmax; jt++) {
        if (jt < jmax) { load_kv(jt + 1, (jt + 1) & 1); CP_WAIT(1); }
        else           { CP_WAIT(0); }
        __syncthreads();
        const uint32_t st = sbase + (jt & 1) * AT_STAGE_B;

        // ---- S = Q K^T (3-pass split)
        float S_[8][4];
#pragma unroll
        for (int i = 0; i < 8; i++)
#pragma unroll
            for (int j = 0; j < 4; j++) S_[i][j] = 0.0f;

#pragma unroll
        for (int ks = 0; ks < 4; ks++)
#pragma unroll
            for (int np = 0; np < 4; np++) {
                uint32_t f0, f1, f2, f3, g0, g1, g2, g3;
                const uint32_t ka = st + np * 16 * AT_STRIDE + b_off + ks * 32;
                LDMATRIX_X4(f0, f1, f2, f3, ka);
                LDMATRIX_X4(g0, g1, g2, g3, ka + AT_TILE_B);
                MMA16816(S_[2 * np], Qh_[ks][0], Qh_[ks][1], Qh_[ks][2],
                         Qh_[ks][3], f0, f1);
                MMA16816(S_[2 * np], Qh_[ks][0], Qh_[ks][1], Qh_[ks][2],
                         Qh_[ks][3], g0, g1);
                MMA16816(S_[2 * np], Ql_[ks][0], Ql_[ks][1], Ql_[ks][2],
                         Ql_[ks][3], f0, f1);
                MMA16816(S_[2 * np + 1], Qh_[ks][0], Qh_[ks][1], Qh_[ks][2],
                         Qh_[ks][3], f2, f3);
                MMA16816(S_[2 * np + 1], Qh_[ks][0], Qh_[ks][1], Qh_[ks][2],
                         Qh_[ks][3], g2, g3);
                MMA16816(S_[2 * np + 1], Ql_[ks][0], Ql_[ks][1], Ql_[ks][2],
                         Ql_[ks][3], f2, f3);
            }

        // ---- scale + causal mask
        const int k0g = jt * 64;
#pragma unroll
        for (int nt = 0; nt < 8; nt++) {
            const int col = k0g + 8 * nt + 2 * (lane & 3);
            S_[nt][0] = (col     > row_lo) ? -1e30f : S_[nt][0] * 0.125f;
            S_[nt][1] = (col + 1 > row_lo) ? -1e30f : S_[nt][1] * 0.125f;
            S_[nt][2] = (col     > row_hi) ? -1e30f : S_[nt][2] * 0.125f;
            S_[nt][3] = (col + 1 > row_hi) ? -1e30f : S_[nt][3] * 0.125f;
        }

        // ---- online softmax (rows split lo/hi; quad reduction over lane&3)
        float rmax_lo = -1e30f, rmax_hi = -1e30f;
#pragma unroll
        for (int nt = 0; nt < 8; nt++) {
            rmax_lo = fmaxf(rmax_lo, fmaxf(S_[nt][0], S_[nt][1]));
            rmax_hi = fmaxf(rmax_hi, fmaxf(S_[nt][2], S_[nt][3]));
        }
        rmax_lo = fmaxf(rmax_lo, __shfl_xor_sync(0xffffffffu, rmax_lo, 1));
        rmax_lo = fmaxf(rmax_lo, __shfl_xor_sync(0xffffffffu, rmax_lo, 2));
        rmax_hi = fmaxf(rmax_hi, __shfl_xor_sync(0xffffffffu, rmax_hi, 1));
        rmax_hi = fmaxf(rmax_hi, __shfl_xor_sync(0xffffffffu, rmax_hi, 2));

        const float mn_lo = fmaxf(m_lo, rmax_lo);
        const float mn_hi = fmaxf(m_hi, rmax_hi);
        const float al_lo = __expf(m_lo - mn_lo);
        const float al_hi = __expf(m_hi - mn_hi);
        m_lo = mn_lo; m_hi = mn_hi;

        float rs_lo = 0.0f, rs_hi = 0.0f;
#pragma unroll
        for (int nt = 0; nt < 8; nt++) {
            S_[nt][0] = __expf(S_[nt][0] - m_lo);
            S_[nt][1] = __expf(S_[nt][1] - m_lo);
            S_[nt][2] = __expf(S_[nt][2] - m_hi);
            S_[nt][3] = __expf(S_[nt][3] - m_hi);
            rs_lo += S_[nt][0] + S_[nt][1];
            rs_hi += S_[nt][2] + S_[nt][3];
        }
        rs_lo += __shfl_xor_sync(0xffffffffu, rs_lo, 1);
        rs_lo += __shfl_xor_sync(0xffffffffu, rs_lo, 2);
        rs_hi += __shfl_xor_sync(0xffffffffu, rs_hi, 1);
        rs_hi += __shfl_xor_sync(0xffffffffu, rs_hi, 2);
        l_lo = l_lo * al_lo + rs_lo;
        l_hi = l_hi * al_hi + rs_hi;

#pragma unroll
        for (int nt = 0; nt < 8; nt++) {
            O_[nt][0] *= al_lo; O_[nt][1] *= al_lo;
            O_[nt][2] *= al_hi; O_[nt][3] *= al_hi;
        }

        // ---- O += P V (P from S regs, 3-pass split; V via ldmatrix.trans)
#pragma unroll
        for (int kp = 0; kp < 4; kp++) {
            uint32_t Ph[4], Pl[4];
            split2(S_[2 * kp][0],     S_[2 * kp][1],     Ph[0], Pl[0]);
            split2(S_[2 * kp][2],     S_[2 * kp][3],     Ph[1], Pl[1]);
            split2(S_[2 * kp + 1][0], S_[2 * kp + 1][1], Ph[2], Pl[2]);
            split2(S_[2 * kp + 1][2], S_[2 * kp + 1][3], Ph[3], Pl[3]);
#pragma unroll
            for (int dp = 0; dp < 4; dp++) {
                uint32_t v0, v1, v2, v3, w0, w1, w2, w3;
                const uint32_t va = st + 2 * AT_TILE_B +
                                    kp * 16 * AT_STRIDE + v_off + dp * 32;
                LDMATRIX_X4_T(v0, v1, v2, v3, va);
                LDMATRIX_X4_T(w0, w1, w2, w3, va + AT_TILE_B);
                MMA16816(O_[2 * dp], Ph[0], Ph[1], Ph[2], Ph[3], v0, v1);
                MMA16816(O_[2 * dp], Ph[0], Ph[1], Ph[2], Ph[3], w0, w1);
                MMA16816(O_[2 * dp], Pl[0], Pl[1], Pl[2], Pl[3], v0, v1);
                MMA16816(O_[2 * dp + 1], Ph[0], Ph[1], Ph[2], Ph[3], v2, v3);
                MMA16816(O_[2 * dp + 1], Ph[0], Ph[1], Ph[2], Ph[3], w2, w3);
                MMA16816(O_[2 * dp + 1], Pl[0], Pl[1], Pl[2], Pl[3], v2, v3);
            }
        }
        __syncthreads();
    }

    // ---- epilogue: normalize, split to bf16 hi/lo, write [B,S,D]
    const float inv_lo = 1.0f / l_lo;
    const float inv_hi = 1.0f / l_hi;
    const int b = bh >> 4;
    const int hh = bh & 15;
#pragma unroll
    for (int nt = 0; nt < 8; nt++) {
        const int col = hh * DKH + 8 * nt + 2 * (lane & 3);
        uint32_t ph, pl;
        split2(O_[nt][0] * inv_lo, O_[nt][1] * inv_lo, ph, pl);
        const size_t i0 = (size_t)(b * SEQ + row_lo) * D_MODEL + col;
        *(uint32_t*)&Ah[i0] = ph;
        *(uint32_t*)&Al[i0] = pl;
        split2(O_[nt][2] * inv_hi, O_[nt][3] * inv_hi, ph, pl);
        const size_t i1 = (size_t)(b * SEQ + row_hi) * D_MODEL + col;
        *(uint32_t*)&Ah[i1] = ph;
        *(uint32_t*)&Al[i1] = pl;
    }
}

// ---------------------------------------------------------------------------
// launch
// ---------------------------------------------------------------------------
extern "C" void kernel_launch(void* const* d_in, const int* in_sizes, int n_in,
                              void* d_out, int out_size)
{
    (void)in_sizes; (void)n_in; (void)out_size;
    const float* x  = (const float*)d_in[0];
    const float* wq = (const float*)d_in[1];
    const float* wk = (const float*)d_in[2];
    const float* wv = (const float*)d_in[3];
    const float* wo = (const float*)d_in[4];
    float* out = (float*)d_out;

    __nv_bfloat16 *xh, *xl, *qh, *ql, *kh, *kl, *vh, *vl, *ah, *al;
    __nv_bfloat16 *wqh, *wql, *wkh, *wkl, *wvh, *wvl, *woh, *wol;
    cudaGetSymbolAddress((void**)&xh, g_xh);
    cudaGetSymbolAddress((void**)&xl, g_xl);
    cudaGetSymbolAddress((void**)&qh, g_qh);
    cudaGetSymbolAddress((void**)&ql, g_ql);
    cudaGetSymbolAddress((void**)&kh, g_kh);
    cudaGetSymbolAddress((void**)&kl, g_kl);
    cudaGetSymbolAddress((void**)&vh, g_vh);
    cudaGetSymbolAddress((void**)&vl, g_vl);
    cudaGetSymbolAddress((void**)&ah, g_ah);
    cudaGetSymbolAddress((void**)&al, g_al);
    cudaGetSymbolAddress((void**)&wqh, g_wqh);
    cudaGetSymbolAddress((void**)&wql, g_wql);
    cudaGetSymbolAddress((void**)&wkh, g_wkh);
    cudaGetSymbolAddress((void**)&wkl, g_wkl);
    cudaGetSymbolAddress((void**)&wvh, g_wvh);
    cudaGetSymbolAddress((void**)&wvl, g_wvl);
    cudaGetSymbolAddress((void**)&woh, g_woh);
    cudaGetSymbolAddress((void**)&wol, g_wol);

    cudaFuncSetAttribute(gemm_bf16_kernel<0>,
                         cudaFuncAttributeMaxDynamicSharedMemorySize, GEMM_SMEM);
    cudaFuncSetAttribute(gemm_bf16_kernel<1>,
                         cudaFuncAttributeMaxDynamicSharedMemorySize, GEMM_SMEM);
    cudaFuncSetAttribute(attn_mma_kernel,
                         cudaFuncAttributeMaxDynamicSharedMemorySize, ATTN_SMEM);

    const int nx4 = MTOK * D_MODEL / 4;
    const int nw4 = D_MODEL * D_MODEL / 4;
    split_kernel<<<(nx4 + 255) / 256, 256>>>(x, xh, xl, nx4);
    split_kernel<<<(nw4 + 255) / 256, 256>>>(wq, wqh, wql, nw4);
    split_kernel<<<(nw4 + 255) / 256, 256>>>(wk, wkh, wkl, nw4);
    split_kernel<<<(nw4 + 255) / 256, 256>>>(wv, wvh, wvl, nw4);
    split_kernel<<<(nw4 + 255) / 256, 256>>>(wo, woh, wol, nw4);

    dim3 ggrid(D_MODEL / BN, MTOK / BM);   // (8, 64)
    gemm_bf16_kernel<0><<<ggrid, 256, GEMM_SMEM>>>(xh, xl, wqh, wql, qh, ql, nullptr);
    gemm_bf16_kernel<0><<<ggrid, 256, GEMM_SMEM>>>(xh, xl, wkh, wkl, kh, kl, nullptr);
    gemm_bf16_kernel<0><<<ggrid, 256, GEMM_SMEM>>>(xh, xl, wvh, wvl, vh, vl, nullptr);

    attn_mma_kernel<<<dim3(SEQ / 128, BATCH * NHEAD), 256, ATTN_SMEM>>>(
        qh, ql, kh, kl, vh, vl, ah, al);

    gemm_bf16_kernel<1><<<ggrid, 256, GEMM_SMEM>>>(ah, al, woh, wol,
                                                   nullptr, nullptr, out);
}

// round 6
// speedup vs baseline: 3.1884x; 1.1828x over previous
#include <cuda_runtime.h>
#include <cuda_bf16.h>
#include <cstdint>
#include <math.h>

#define D_MODEL 1024
#define NHEAD 16
#define DKH 64
#define BATCH 4
#define SEQ 2048
#define MTOK (BATCH * SEQ)   // 8192

// ---------------------------------------------------------------------------
// Scratch (alloc-free rule: __device__ globals)
// ---------------------------------------------------------------------------
__device__ __nv_bfloat16 g_xh[MTOK * D_MODEL];
__device__ __nv_bfloat16 g_xl[MTOK * D_MODEL];
__device__ __nv_bfloat16 g_qh[MTOK * D_MODEL];   // [B,H,S,64]
__device__ __nv_bfloat16 g_ql[MTOK * D_MODEL];
__device__ __nv_bfloat16 g_kh[MTOK * D_MODEL];
__device__ __nv_bfloat16 g_kl[MTOK * D_MODEL];
__device__ __nv_bfloat16 g_vh[MTOK * D_MODEL];
__device__ __nv_bfloat16 g_vl[MTOK * D_MODEL];
__device__ __nv_bfloat16 g_ah[MTOK * D_MODEL];   // attn out [B,S,D]
__device__ __nv_bfloat16 g_al[MTOK * D_MODEL];
__device__ __nv_bfloat16 g_wqh[D_MODEL * D_MODEL];
__device__ __nv_bfloat16 g_wql[D_MODEL * D_MODEL];
__device__ __nv_bfloat16 g_wkh[D_MODEL * D_MODEL];
__device__ __nv_bfloat16 g_wkl[D_MODEL * D_MODEL];
__device__ __nv_bfloat16 g_wvh[D_MODEL * D_MODEL];
__device__ __nv_bfloat16 g_wvl[D_MODEL * D_MODEL];
__device__ __nv_bfloat16 g_woh[D_MODEL * D_MODEL];
__device__ __nv_bfloat16 g_wol[D_MODEL * D_MODEL];

// ---------------------------------------------------------------------------
// helpers (arch-portable only: cp.async / ldmatrix / mma.sync)
// ---------------------------------------------------------------------------
__device__ __forceinline__ uint32_t smem_u32(const void* p) {
    uint32_t a;
    asm("{ .reg .u64 t; cvta.to.shared.u64 t, %1; cvt.u32.u64 %0, t; }"
        : "=r"(a) : "l"(p));
    return a;
}

#define LDMATRIX_X4(r0, r1, r2, r3, addr) \
    asm volatile("ldmatrix.sync.aligned.m8n8.x4.shared.b16 {%0,%1,%2,%3}, [%4];" \
        : "=r"(r0), "=r"(r1), "=r"(r2), "=r"(r3) : "r"(addr))

#define LDMATRIX_X4_T(r0, r1, r2, r3, addr) \
    asm volatile("ldmatrix.sync.aligned.m8n8.x4.trans.shared.b16 {%0,%1,%2,%3}, [%4];" \
        : "=r"(r0), "=r"(r1), "=r"(r2), "=r"(r3) : "r"(addr))

#define MMA16816(d, a0, a1, a2, a3, b0, b1) \
    asm volatile("mma.sync.aligned.m16n8k16.row.col.f32.bf16.bf16.f32 " \
        "{%0,%1,%2,%3}, {%4,%5,%6,%7}, {%8,%9}, {%0,%1,%2,%3};" \
        : "+f"((d)[0]), "+f"((d)[1]), "+f"((d)[2]), "+f"((d)[3]) \
        : "r"(a0), "r"(a1), "r"(a2), "r"(a3), "r"(b0), "r"(b1))

#define CP_ASYNC16(saddr, gaddr) \
    asm volatile("cp.async.cg.shared.global [%0], [%1], 16;" \
        :: "r"(saddr), "l"(gaddr))
#define CP_COMMIT() asm volatile("cp.async.commit_group;" ::: "memory")
#define CP_WAIT(n)  asm volatile("cp.async.wait_group %0;" :: "n"(n) : "memory")

#define PACK_BF16X2(r, lo, hi) \
    asm("cvt.rn.bf16x2.f32 %0, %1, %2;" : "=r"(r) : "f"(hi), "f"(lo))

__device__ __forceinline__ void split2(float v0, float v1,
                                       uint32_t& ph, uint32_t& pl) {
    PACK_BF16X2(ph, v0, v1);
    const float f0 = __uint_as_float(ph << 16);
    const float f1 = __uint_as_float(ph & 0xffff0000u);
    PACK_BF16X2(pl, v0 - f0, v1 - f1);
}

// ---------------------------------------------------------------------------
// fp32 -> bf16 hi/lo splits
// ---------------------------------------------------------------------------
__global__ void __launch_bounds__(256) split_kernel(
    const float* __restrict__ in,
    __nv_bfloat16* __restrict__ hi, __nv_bfloat16* __restrict__ lo, int n4)
{
    int i = blockIdx.x * 256 + threadIdx.x;
    if (i >= n4) return;
    float4 v = ((const float4*)in)[i];
    uint32_t h01, l01, h23, l23;
    split2(v.x, v.y, h01, l01);
    split2(v.z, v.w, h23, l23);
    ((uint32_t*)hi)[2 * i]     = h01;
    ((uint32_t*)hi)[2 * i + 1] = h23;
    ((uint32_t*)lo)[2 * i]     = l01;
    ((uint32_t*)lo)[2 * i + 1] = l23;
}

#define NW4 (D_MODEL * D_MODEL / 4)

__global__ void __launch_bounds__(256) split4_kernel(
    const float* __restrict__ w0, const float* __restrict__ w1,
    const float* __restrict__ w2, const float* __restrict__ w3,
    __nv_bfloat16* __restrict__ h0, __nv_bfloat16* __restrict__ l0,
    __nv_bfloat16* __restrict__ h1, __nv_bfloat16* __restrict__ l1,
    __nv_bfloat16* __restrict__ h2, __nv_bfloat16* __restrict__ l2,
    __nv_bfloat16* __restrict__ h3, __nv_bfloat16* __restrict__ l3)
{
    int id = blockIdx.x * 256 + threadIdx.x;
    const int which = id / NW4;
    const int i = id - which * NW4;
    const float* in = (which == 0) ? w0 : (which == 1) ? w1
                      : (which == 2) ? w2 : w3;
    __nv_bfloat16* hi = (which == 0) ? h0 : (which == 1) ? h1
                        : (which == 2) ? h2 : h3;
    __nv_bfloat16* lo = (which == 0) ? l0 : (which == 1) ? l1
                        : (which == 2) ? l2 : l3;
    float4 v = ((const float4*)in)[i];
    uint32_t h01, l01, h23, l23;
    split2(v.x, v.y, h01, l01);
    split2(v.z, v.w, h23, l23);
    ((uint32_t*)hi)[2 * i]     = h01;
    ((uint32_t*)hi)[2 * i + 1] = h23;
    ((uint32_t*)lo)[2 * i]     = l01;
    ((uint32_t*)lo)[2 * i + 1] = l23;
}

// ---------------------------------------------------------------------------
// mma.sync bf16-split GEMM body: C[m,n] = sum_k A[m,k]*B[n,k]
// 128x128 tile/CTA, BK=32, 2-stage cp.async pipeline, 2 CTAs/SM.
// MODE 0: write bf16 hi/lo head-split [B,H,S,dk]; MODE 1: fp32 [M, D_MODEL].
// ---------------------------------------------------------------------------
#define BM 128
#define BN 128
#define BK 32
#define CHUNKS (D_MODEL / BK)
#define TPAD 40
#define TILE_B (128 * TPAD * 2)
#define STAGE_B (4 * TILE_B)
#define GEMM_SMEM (2 * STAGE_B)        // 81920

template <int MODE>
__device__ __forceinline__ void gemm_body(
    const __nv_bfloat16* __restrict__ Ah, const __nv_bfloat16* __restrict__ Al,
    const __nv_bfloat16* __restrict__ Bh, const __nv_bfloat16* __restrict__ Bl,
    __nv_bfloat16* __restrict__ Ch, __nv_bfloat16* __restrict__ Cl,
    float* __restrict__ Cf, const int bm, const int bn)
{
    extern __shared__ __align__(128) char smem[];
    const uint32_t sbase = smem_u32(smem);
    const int tid  = threadIdx.x;
    const int wid  = tid >> 5;
    const int lane = tid & 31;
    const int K = D_MODEL;

    const int warp_m = wid >> 2;
    const int warp_n = wid & 3;

    auto load_stage = [&](int chunk, int s) {
        const uint32_t st = sbase + s * STAGE_B;
        const int k0 = chunk * BK;
#pragma unroll
        for (int u = 0; u < 8; u++) {
            const int id = u * 256 + tid;
            const int t = id >> 9;
            const int idx = id & 511;
            const int row = idx >> 2;
            const int c = idx & 3;
            const __nv_bfloat16* g;
            int grow;
            if (t == 0)      { g = Ah; grow = bm + row; }
            else if (t == 1) { g = Al; grow = bm + row; }
            else if (t == 2) { g = Bh; grow = bn + row; }
            else             { g = Bl; grow = bn + row; }
            const __nv_bfloat16* gaddr = g + (size_t)grow * K + k0 + c * 8;
            const uint32_t saddr = st + t * TILE_B + row * (TPAD * 2) + c * 16;
            CP_ASYNC16(saddr, gaddr);
        }
        CP_COMMIT();
    };

    load_stage(0, 0);
    load_stage(1, 1);

    float acc[4][4][4];
#pragma unroll
    for (int i = 0; i < 4; i++)
#pragma unroll
        for (int j = 0; j < 4; j++)
#pragma unroll
            for (int r = 0; r < 4; r++) acc[i][j][r] = 0.0f;

    const int a_row = warp_m * 64 + (lane & 15);
    const uint32_t a_off = a_row * (TPAD * 2) + (lane >> 4) * 16;
    const int b_row = warp_n * 32 + ((lane >> 4) & 1) * 8 + (lane & 7);
    const uint32_t b_off = b_row * (TPAD * 2) + ((lane >> 3) & 1) * 16;

    for (int chunk = 0; chunk < CHUNKS; chunk++) {
        const int s = chunk & 1;
        if (chunk < CHUNKS - 1) CP_WAIT(1);
        else                    CP_WAIT(0);
        __syncthreads();
        const uint32_t st = sbase + s * STAGE_B;
        const uint32_t aH = st + a_off;
        const uint32_t aL = st + TILE_B + a_off;
        const uint32_t bH = st + 2 * TILE_B + b_off;
        const uint32_t bL = st + 3 * TILE_B + b_off;

#pragma unroll
        for (int ks = 0; ks < 2; ks++) {
            const uint32_t kb = ks * 32;
            uint32_t fAH[4][4], fAL[4][4], fBH[4][2], fBL[4][2];
#pragma unroll
            for (int mt = 0; mt < 4; mt++) {
                LDMATRIX_X4(fAH[mt][0], fAH[mt][1], fAH[mt][2], fAH[mt][3],
                            aH + mt * 16 * (TPAD * 2) + kb);
                LDMATRIX_X4(fAL[mt][0], fAL[mt][1], fAL[mt][2], fAL[mt][3],
                            aL + mt * 16 * (TPAD * 2) + kb);
            }
#pragma unroll
            for (int np = 0; np < 2; np++) {
                LDMATRIX_X4(fBH[2 * np][0], fBH[2 * np][1],
                            fBH[2 * np + 1][0], fBH[2 * np + 1][1],
                            bH + np * 16 * (TPAD * 2) + kb);
                LDMATRIX_X4(fBL[2 * np][0], fBL[2 * np][1],
                            fBL[2 * np + 1][0], fBL[2 * np + 1][1],
                            bL + np * 16 * (TPAD * 2) + kb);
            }
#pragma unroll
            for (int mt = 0; mt < 4; mt++)
#pragma unroll
                for (int nt = 0; nt < 4; nt++) {
                    MMA16816(acc[mt][nt], fAH[mt][0], fAH[mt][1], fAH[mt][2],
                             fAH[mt][3], fBH[nt][0], fBH[nt][1]);
                    MMA16816(acc[mt][nt], fAH[mt][0], fAH[mt][1], fAH[mt][2],
                             fAH[mt][3], fBL[nt][0], fBL[nt][1]);
                    MMA16816(acc[mt][nt], fAL[mt][0], fAL[mt][1], fAL[mt][2],
                             fAL[mt][3], fBH[nt][0], fBH[nt][1]);
                }
        }
        __syncthreads();
        if (chunk + 2 < CHUNKS) load_stage(chunk + 2, s);
    }

#pragma unroll
    for (int mt = 0; mt < 4; mt++) {
#pragma unroll
        for (int half = 0; half < 2; half++) {
            const int m = bm + warp_m * 64 + mt * 16 + (lane >> 2) + half * 8;
#pragma unroll
            for (int nt = 0; nt < 4; nt++) {
                const int n = bn + warp_n * 32 + nt * 8 + (lane & 3) * 2;
                const float v0 = acc[mt][nt][2 * half];
                const float v1 = acc[mt][nt][2 * half + 1];
                if (MODE == 0) {
                    const int b = m >> 11;
                    const int sq = m & 2047;
                    const int h = n >> 6;
                    const int dd = n & 63;
                    const size_t idx =
                        ((size_t)((b * NHEAD + h) * SEQ + sq) << 6) + dd;
                    uint32_t ph, pl;
                    split2(v0, v1, ph, pl);
                    *(uint32_t*)&Ch[idx] = ph;
                    *(uint32_t*)&Cl[idx] = pl;
                } else {
                    const size_t idx = (size_t)m * D_MODEL + n;
                    *(float2*)&Cf[idx] = make_float2(v0, v1);
                }
            }
        }
    }
}

// Fused QKV projection: grid.x = 24 (proj = x>>3), grid.y = 64
__global__ void __launch_bounds__(256, 2) gemm_qkv_kernel(
    const __nv_bfloat16* __restrict__ xh, const __nv_bfloat16* __restrict__ xl,
    const __nv_bfloat16* __restrict__ wqh, const __nv_bfloat16* __restrict__ wql,
    const __nv_bfloat16* __restrict__ wkh, const __nv_bfloat16* __restrict__ wkl,
    const __nv_bfloat16* __restrict__ wvh, const __nv_bfloat16* __restrict__ wvl,
    __nv_bfloat16* __restrict__ qh, __nv_bfloat16* __restrict__ ql,
    __nv_bfloat16* __restrict__ kh, __nv_bfloat16* __restrict__ kl,
    __nv_bfloat16* __restrict__ vh, __nv_bfloat16* __restrict__ vl)
{
    const int proj = blockIdx.x >> 3;
    const int bn = (blockIdx.x & 7) * BN;
    const int bm = blockIdx.y * BM;
    const __nv_bfloat16* Bh = (proj == 0) ? wqh : (proj == 1) ? wkh : wvh;
    const __nv_bfloat16* Bl = (proj == 0) ? wql : (proj == 1) ? wkl : wvl;
    __nv_bfloat16* Ch = (proj == 0) ? qh : (proj == 1) ? kh : vh;
    __nv_bfloat16* Cl = (proj == 0) ? ql : (proj == 1) ? kl : vl;
    gemm_body<0>(xh, xl, Bh, Bl, Ch, Cl, nullptr, bm, bn);
}

// Output projection: fp32 result
__global__ void __launch_bounds__(256, 2) gemm_out_kernel(
    const __nv_bfloat16* __restrict__ ah, const __nv_bfloat16* __restrict__ al,
    const __nv_bfloat16* __restrict__ woh, const __nv_bfloat16* __restrict__ wol,
    float* __restrict__ out)
{
    gemm_body<1>(ah, al, woh, wol, nullptr, nullptr, out,
                 blockIdx.y * BM, blockIdx.x * BN);
}

// ---------------------------------------------------------------------------
// Tensor-core causal flash attention (bf16 hi/lo split, fp32 accum).
// ---------------------------------------------------------------------------
#define ATPAD 72
#define AT_STRIDE (ATPAD * 2)          // 144 bytes/row
#define AT_TILE_B (64 * AT_STRIDE)     // 9216
#define AT_STAGE_B (4 * AT_TILE_B)     // 36864 (Kh,Kl,Vh,Vl)
#define ATTN_SMEM (2 * AT_STAGE_B)     // 73728

__global__ void __launch_bounds__(256) attn_mma_kernel(
    const __nv_bfloat16* __restrict__ Qh, const __nv_bfloat16* __restrict__ Ql,
    const __nv_bfloat16* __restrict__ Kh, const __nv_bfloat16* __restrict__ Kl,
    const __nv_bfloat16* __restrict__ Vh, const __nv_bfloat16* __restrict__ Vl,
    __nv_bfloat16* __restrict__ Ah, __nv_bfloat16* __restrict__ Al)
{
    extern __shared__ __align__(128) char smem[];
    const uint32_t sbase = smem_u32(smem);
    const int tid  = threadIdx.x;
    const int wid  = tid >> 5;
    const int lane = tid & 31;
    const int bh = blockIdx.y;
    const int qb = blockIdx.x;
    const int q0 = qb * 128;
    const size_t base_off = (size_t)bh * SEQ * DKH;

#pragma unroll
    for (int u = 0; u < 8; u++) {
        const int id = u * 256 + tid;
        const int t = id >> 10;
        const int idx = id & 1023;
        const int row = idx >> 3;
        const int c = idx & 7;
        const __nv_bfloat16* g = t ? Ql : Qh;
        CP_ASYNC16(sbase + t * (128 * AT_STRIDE) + row * AT_STRIDE + c * 16,
                   g + base_off + (size_t)(q0 + row) * DKH + c * 8);
    }
    CP_COMMIT();
    CP_WAIT(0);
    __syncthreads();

    uint32_t Qh_[4][4], Ql_[4][4];
    {
        const uint32_t qa =
            sbase + (16 * wid + (lane & 15)) * AT_STRIDE + (lane >> 4) * 16;
#pragma unroll
        for (int ks = 0; ks < 4; ks++) {
            LDMATRIX_X4(Qh_[ks][0], Qh_[ks][1], Qh_[ks][2], Qh_[ks][3],
                        qa + ks * 32);
            LDMATRIX_X4(Ql_[ks][0], Ql_[ks][1], Ql_[ks][2], Ql_[ks][3],
                        qa + 128 * AT_STRIDE + ks * 32);
        }
    }
    __syncthreads();

    auto load_kv = [&](int jt, int buf) {
        const uint32_t st = sbase + buf * AT_STAGE_B;
        const int k0 = jt * 64;
#pragma unroll
        for (int u = 0; u < 8; u++) {
            const int id = u * 256 + tid;
            const int t = id >> 9;
            const int idx = id & 511;
            const int row = idx >> 3;
            const int c = idx & 7;
            const __nv_bfloat16* g = (t == 0) ? Kh : (t == 1) ? Kl
                                     : (t == 2) ? Vh : Vl;
            CP_ASYNC16(st + t * AT_TILE_B + row * AT_STRIDE + c * 16,
                       g + base_off + (size_t)(k0 + row) * DKH + c * 8);
        }
        CP_COMMIT();
    };

    float O_[8][4];
#pragma unroll
    for (int i = 0; i < 8; i++)
#pragma unroll
        for (int j = 0; j < 4; j++) O_[i][j] = 0.0f;
    float m_lo = -1e30f, m_hi = -1e30f, l_lo = 0.0f, l_hi = 0.0f;

    const int row_lo = q0 + 16 * wid + (lane >> 2);
    const int row_hi = row_lo + 8;
    const uint32_t b_off =
        (((lane >> 4) & 1) * 8 + (lane & 7)) * AT_STRIDE + ((lane >> 3) & 1) * 16;
    const uint32_t v_off = (lane & 15) * AT_STRIDE + (lane >> 4) * 16;

    const int jmax = 2 * qb + 1;
    load_kv(0, 0);

    for (int jt = 0; jt <= jmax; jt++) {
        if (jt < jmax) { load_kv(jt + 1, (jt + 1) & 1); CP_WAIT(1); }
        else           { CP_WAIT(0); }
        __syncthreads();
        const uint32_t st = sbase + (jt & 1) * AT_STAGE_B;

        float S_[8][4];
#pragma unroll
        for (int i = 0; i < 8; i++)
#pragma unroll
            for (int j = 0; j < 4; j++) S_[i][j] = 0.0f;

#pragma unroll
        for (int ks = 0; ks < 4; ks++)
#pragma unroll
            for (int np = 0; np < 4; np++) {
                uint32_t f0, f1, f2, f3, g0, g1, g2, g3;
                const uint32_t ka = st + np * 16 * AT_STRIDE + b_off + ks * 32;
                LDMATRIX_X4(f0, f1, f2, f3, ka);
                LDMATRIX_X4(g0, g1, g2, g3, ka + AT_TILE_B);
                MMA16816(S_[2 * np], Qh_[ks][0], Qh_[ks][1], Qh_[ks][2],
                         Qh_[ks][3], f0, f1);
                MMA16816(S_[2 * np], Qh_[ks][0], Qh_[ks][1], Qh_[ks][2],
                         Qh_[ks][3], g0, g1);
                MMA16816(S_[2 * np], Ql_[ks][0], Ql_[ks][1], Ql_[ks][2],
                         Ql_[ks][3], f0, f1);
                MMA16816(S_[2 * np + 1], Qh_[ks][0], Qh_[ks][1], Qh_[ks][2],
                         Qh_[ks][3], f2, f3);
                MMA16816(S_[2 * np + 1], Qh_[ks][0], Qh_[ks][1], Qh_[ks][2],
                         Qh_[ks][3], g2, g3);
                MMA16816(S_[2 * np + 1], Ql_[ks][0], Ql_[ks][1], Ql_[ks][2],
                         Ql_[ks][3], f2, f3);
            }

        const int k0g = jt * 64;
#pragma unroll
        for (int nt = 0; nt < 8; nt++) {
            const int col = k0g + 8 * nt + 2 * (lane & 3);
            S_[nt][0] = (col     > row_lo) ? -1e30f : S_[nt][0] * 0.125f;
            S_[nt][1] = (col + 1 > row_lo) ? -1e30f : S_[nt][1] * 0.125f;
            S_[nt][2] = (col     > row_hi) ? -1e30f : S_[nt][2] * 0.125f;
            S_[nt][3] = (col + 1 > row_hi) ? -1e30f : S_[nt][3] * 0.125f;
        }

        float rmax_lo = -1e30f, rmax_hi = -1e30f;
#pragma unroll
        for (int nt = 0; nt < 8; nt++) {
            rmax_lo = fmaxf(rmax_lo, fmaxf(S_[nt][0], S_[nt][1]));
            rmax_hi = fmaxf(rmax_hi, fmaxf(S_[nt][2], S_[nt][3]));
        }
        rmax_lo = fmaxf(rmax_lo, __shfl_xor_sync(0xffffffffu, rmax_lo, 1));
        rmax_lo = fmaxf(rmax_lo, __shfl_xor_sync(0xffffffffu, rmax_lo, 2));
        rmax_hi = fmaxf(rmax_hi, __shfl_xor_sync(0xffffffffu, rmax_hi, 1));
        rmax_hi = fmaxf(rmax_hi, __shfl_xor_sync(0xffffffffu, rmax_hi, 2));

        const float mn_lo = fmaxf(m_lo, rmax_lo);
        const float mn_hi = fmaxf(m_hi, rmax_hi);
        const float al_lo = __expf(m_lo - mn_lo);
        const float al_hi = __expf(m_hi - mn_hi);
        m_lo = mn_lo; m_hi = mn_hi;

        float rs_lo = 0.0f, rs_hi = 0.0f;
#pragma unroll
        for (int nt = 0; nt < 8; nt++) {
            S_[nt][0] = __expf(S_[nt][0] - m_lo);
            S_[nt][1] = __expf(S_[nt][1] - m_lo);
            S_[nt][2] = __expf(S_[nt][2] - m_hi);
            S_[nt][3] = __expf(S_[nt][3] - m_hi);
            rs_lo += S_[nt][0] + S_[nt][1];
            rs_hi += S_[nt][2] + S_[nt][3];
        }
        rs_lo += __shfl_xor_sync(0xffffffffu, rs_lo, 1);
        rs_lo += __shfl_xor_sync(0xffffffffu, rs_lo, 2);
        rs_hi += __shfl_xor_sync(0xffffffffu, rs_hi, 1);
        rs_hi += __shfl_xor_sync(0xffffffffu, rs_hi, 2);
        l_lo = l_lo * al_lo + rs_lo;
        l_hi = l_hi * al_hi + rs_hi;

#pragma unroll
        for (int nt = 0; nt < 8; nt++) {
            O_[nt][0] *= al_lo; O_[nt][1] *= al_lo;
            O_[nt][2] *= al_hi; O_[nt][3] *= al_hi;
        }

#pragma unroll
        for (int kp = 0; kp < 4; kp++) {
            uint32_t Ph[4], Pl[4];
            split2(S_[2 * kp][0],     S_[2 * kp][1],     Ph[0], Pl[0]);
            split2(S_[2 * kp][2],     S_[2 * kp][3],     Ph[1], Pl[1]);
            split2(S_[2 * kp + 1][0], S_[2 * kp + 1][1], Ph[2], Pl[2]);
            split2(S_[2 * kp + 1][2], S_[2 * kp + 1][3], Ph[3], Pl[3]);
#pragma unroll
            for (int dp = 0; dp < 4; dp++) {
                uint32_t v0, v1, v2, v3, w0, w1, w2, w3;
                const uint32_t va = st + 2 * AT_TILE_B +
                                    kp * 16 * AT_STRIDE + v_off + dp * 32;
                LDMATRIX_X4_T(v0, v1, v2, v3, va);
                LDMATRIX_X4_T(w0, w1, w2, w3, va + AT_TILE_B);
                MMA16816(O_[2 * dp], Ph[0], Ph[1], Ph[2], Ph[3], v0, v1);
                MMA16816(O_[2 * dp], Ph[0], Ph[1], Ph[2], Ph[3], w0, w1);
                MMA16816(O_[2 * dp], Pl[0], Pl[1], Pl[2], Pl[3], v0, v1);
                MMA16816(O_[2 * dp + 1], Ph[0], Ph[1], Ph[2], Ph[3], v2, v3);
                MMA16816(O_[2 * dp + 1], Ph[0], Ph[1], Ph[2], Ph[3], w2, w3);
                MMA16816(O_[2 * dp + 1], Pl[0], Pl[1], Pl[2], Pl[3], v2, v3);
            }
        }
        __syncthreads();
    }

    const float inv_lo = 1.0f / l_lo;
    const float inv_hi = 1.0f / l_hi;
    const int b = bh >> 4;
    const int hh = bh & 15;
#pragma unroll
    for (int nt = 0; nt < 8; nt++) {
        const int col = hh * DKH + 8 * nt + 2 * (lane & 3);
        uint32_t ph, pl;
        split2(O_[nt][0] * inv_lo, O_[nt][1] * inv_lo, ph, pl);
        const size_t i0 = (size_t)(b * SEQ + row_lo) * D_MODEL + col;
        *(uint32_t*)&Ah[i0] = ph;
        *(uint32_t*)&Al[i0] = pl;
        split2(O_[nt][2] * inv_hi, O_[nt][3] * inv_hi, ph, pl);
        const size_t i1 = (size_t)(b * SEQ + row_hi) * D_MODEL + col;
        *(uint32_t*)&Ah[i1] = ph;
        *(uint32_t*)&Al[i1] = pl;
    }
}

// ---------------------------------------------------------------------------
// launch
// ---------------------------------------------------------------------------
extern "C" void kernel_launch(void* const* d_in, const int* in_sizes, int n_in,
                              void* d_out, int out_size)
{
    (void)in_sizes; (void)n_in; (void)out_size;
    const float* x  = (const float*)d_in[0];
    const float* wq = (const float*)d_in[1];
    const float* wk = (const float*)d_in[2];
    const float* wv = (const float*)d_in[3];
    const float* wo = (const float*)d_in[4];
    float* out = (float*)d_out;

    __nv_bfloat16 *xh, *xl, *qh, *ql, *kh, *kl, *vh, *vl, *ah, *al;
    __nv_bfloat16 *wqh, *wql, *wkh, *wkl, *wvh, *wvl, *woh, *wol;
    cudaGetSymbolAddress((void**)&xh, g_xh);
    cudaGetSymbolAddress((void**)&xl, g_xl);
    cudaGetSymbolAddress((void**)&qh, g_qh);
    cudaGetSymbolAddress((void**)&ql, g_ql);
    cudaGetSymbolAddress((void**)&kh, g_kh);
    cudaGetSymbolAddress((void**)&kl, g_kl);
    cudaGetSymbolAddress((void**)&vh, g_vh);
    cudaGetSymbolAddress((void**)&vl, g_vl);
    cudaGetSymbolAddress((void**)&ah, g_ah);
    cudaGetSymbolAddress((void**)&al, g_al);
    cudaGetSymbolAddress((void**)&wqh, g_wqh);
    cudaGetSymbolAddress((void**)&wql, g_wql);
    cudaGetSymbolAddress((void**)&wkh, g_wkh);
    cudaGetSymbolAddress((void**)&wkl, g_wkl);
    cudaGetSymbolAddress((void**)&wvh, g_wvh);
    cudaGetSymbolAddress((void**)&wvl, g_wvl);
    cudaGetSymbolAddress((void**)&woh, g_woh);
    cudaGetSymbolAddress((void**)&wol, g_wol);

    cudaFuncSetAttribute(gemm_qkv_kernel,
                         cudaFuncAttributeMaxDynamicSharedMemorySize, GEMM_SMEM);
    cudaFuncSetAttribute(gemm_out_kernel,
                         cudaFuncAttributeMaxDynamicSharedMemorySize, GEMM_SMEM);
    cudaFuncSetAttribute(attn_mma_kernel,
                         cudaFuncAttributeMaxDynamicSharedMemorySize, ATTN_SMEM);

    const int nx4 = MTOK * D_MODEL / 4;
    split_kernel<<<(nx4 + 255) / 256, 256>>>(x, xh, xl, nx4);
    split4_kernel<<<(4 * NW4 + 255) / 256, 256>>>(
        wq, wk, wv, wo, wqh, wql, wkh, wkl, wvh, wvl, woh, wol);

    gemm_qkv_kernel<<<dim3(24, MTOK / BM), 256, GEMM_SMEM>>>(
        xh, xl, wqh, wql, wkh, wkl, wvh, wvl, qh, ql, kh, kl, vh, vl);

    attn_mma_kernel<<<dim3(SEQ / 128, BATCH * NHEAD), 256, ATTN_SMEM>>>(
        qh, ql, kh, kl, vh, vl, ah, al);

    gemm_out_kernel<<<dim3(D_MODEL / BN, MTOK / BM), 256, GEMM_SMEM>>>(
        ah, al, woh, wol, out);
}

// round 7
// speedup vs baseline: 3.2863x; 1.0307x over previous
#include <cuda_runtime.h>
#include <cuda_bf16.h>
#include <cstdint>
#include <math.h>

#define D_MODEL 1024
#define NHEAD 16
#define DKH 64
#define BATCH 4
#define SEQ 2048
#define MTOK (BATCH * SEQ)   // 8192

// ---------------------------------------------------------------------------
// Scratch (alloc-free rule: __device__ globals)
// ---------------------------------------------------------------------------
__device__ __nv_bfloat16 g_xh[MTOK * D_MODEL];
__device__ __nv_bfloat16 g_xl[MTOK * D_MODEL];
__device__ __nv_bfloat16 g_qh[MTOK * D_MODEL];   // [B,H,S,64]
__device__ __nv_bfloat16 g_ql[MTOK * D_MODEL];
__device__ __nv_bfloat16 g_kh[MTOK * D_MODEL];
__device__ __nv_bfloat16 g_kl[MTOK * D_MODEL];
__device__ __nv_bfloat16 g_vh[MTOK * D_MODEL];
__device__ __nv_bfloat16 g_vl[MTOK * D_MODEL];
__device__ __nv_bfloat16 g_ah[MTOK * D_MODEL];   // attn out [B,S,D]
__device__ __nv_bfloat16 g_al[MTOK * D_MODEL];
__device__ __nv_bfloat16 g_wqh[D_MODEL * D_MODEL];
__device__ __nv_bfloat16 g_wql[D_MODEL * D_MODEL];
__device__ __nv_bfloat16 g_wkh[D_MODEL * D_MODEL];
__device__ __nv_bfloat16 g_wkl[D_MODEL * D_MODEL];
__device__ __nv_bfloat16 g_wvh[D_MODEL * D_MODEL];
__device__ __nv_bfloat16 g_wvl[D_MODEL * D_MODEL];
__device__ __nv_bfloat16 g_woh[D_MODEL * D_MODEL];
__device__ __nv_bfloat16 g_wol[D_MODEL * D_MODEL];

// ---------------------------------------------------------------------------
// helpers (arch-portable only: cp.async / ldmatrix / mma.sync)
// ---------------------------------------------------------------------------
__device__ __forceinline__ uint32_t smem_u32(const void* p) {
    uint32_t a;
    asm("{ .reg .u64 t; cvta.to.shared.u64 t, %1; cvt.u32.u64 %0, t; }"
        : "=r"(a) : "l"(p));
    return a;
}

#define LDMATRIX_X4(r0, r1, r2, r3, addr) \
    asm volatile("ldmatrix.sync.aligned.m8n8.x4.shared.b16 {%0,%1,%2,%3}, [%4];" \
        : "=r"(r0), "=r"(r1), "=r"(r2), "=r"(r3) : "r"(addr))

#define LDMATRIX_X4_T(r0, r1, r2, r3, addr) \
    asm volatile("ldmatrix.sync.aligned.m8n8.x4.trans.shared.b16 {%0,%1,%2,%3}, [%4];" \
        : "=r"(r0), "=r"(r1), "=r"(r2), "=r"(r3) : "r"(addr))

#define MMA16816(d, a0, a1, a2, a3, b0, b1) \
    asm volatile("mma.sync.aligned.m16n8k16.row.col.f32.bf16.bf16.f32 " \
        "{%0,%1,%2,%3}, {%4,%5,%6,%7}, {%8,%9}, {%0,%1,%2,%3};" \
        : "+f"((d)[0]), "+f"((d)[1]), "+f"((d)[2]), "+f"((d)[3]) \
        : "r"(a0), "r"(a1), "r"(a2), "r"(a3), "r"(b0), "r"(b1))

#define CP_ASYNC16(saddr, gaddr) \
    asm volatile("cp.async.cg.shared.global [%0], [%1], 16;" \
        :: "r"(saddr), "l"(gaddr))
#define CP_COMMIT() asm volatile("cp.async.commit_group;" ::: "memory")
#define CP_WAIT(n)  asm volatile("cp.async.wait_group %0;" :: "n"(n) : "memory")

#define PACK_BF16X2(r, lo, hi) \
    asm("cvt.rn.bf16x2.f32 %0, %1, %2;" : "=r"(r) : "f"(hi), "f"(lo))

__device__ __forceinline__ void split2(float v0, float v1,
                                       uint32_t& ph, uint32_t& pl) {
    PACK_BF16X2(ph, v0, v1);
    const float f0 = __uint_as_float(ph << 16);
    const float f1 = __uint_as_float(ph & 0xffff0000u);
    PACK_BF16X2(pl, v0 - f0, v1 - f1);
}

// ---------------------------------------------------------------------------
// fp32 -> bf16 hi/lo splits
// ---------------------------------------------------------------------------
__global__ void __launch_bounds__(256) split_kernel(
    const float* __restrict__ in,
    __nv_bfloat16* __restrict__ hi, __nv_bfloat16* __restrict__ lo, int n4)
{
    int i = blockIdx.x * 256 + threadIdx.x;
    if (i >= n4) return;
    float4 v = ((const float4*)in)[i];
    uint32_t h01, l01, h23, l23;
    split2(v.x, v.y, h01, l01);
    split2(v.z, v.w, h23, l23);
    ((uint32_t*)hi)[2 * i]     = h01;
    ((uint32_t*)hi)[2 * i + 1] = h23;
    ((uint32_t*)lo)[2 * i]     = l01;
    ((uint32_t*)lo)[2 * i + 1] = l23;
}

#define NW4 (D_MODEL * D_MODEL / 4)

__global__ void __launch_bounds__(256) split4_kernel(
    const float* __restrict__ w0, const float* __restrict__ w1,
    const float* __restrict__ w2, const float* __restrict__ w3,
    __nv_bfloat16* __restrict__ h0, __nv_bfloat16* __restrict__ l0,
    __nv_bfloat16* __restrict__ h1, __nv_bfloat16* __restrict__ l1,
    __nv_bfloat16* __restrict__ h2, __nv_bfloat16* __restrict__ l2,
    __nv_bfloat16* __restrict__ h3, __nv_bfloat16* __restrict__ l3)
{
    int id = blockIdx.x * 256 + threadIdx.x;
    const int which = id / NW4;
    const int i = id - which * NW4;
    const float* in = (which == 0) ? w0 : (which == 1) ? w1
                      : (which == 2) ? w2 : w3;
    __nv_bfloat16* hi = (which == 0) ? h0 : (which == 1) ? h1
                        : (which == 2) ? h2 : h3;
    __nv_bfloat16* lo = (which == 0) ? l0 : (which == 1) ? l1
                        : (which == 2) ? l2 : l3;
    float4 v = ((const float4*)in)[i];
    uint32_t h01, l01, h23, l23;
    split2(v.x, v.y, h01, l01);
    split2(v.z, v.w, h23, l23);
    ((uint32_t*)hi)[2 * i]     = h01;
    ((uint32_t*)hi)[2 * i + 1] = h23;
    ((uint32_t*)lo)[2 * i]     = l01;
    ((uint32_t*)lo)[2 * i + 1] = l23;
}

// ---------------------------------------------------------------------------
// mma.sync bf16-split GEMM body (unchanged from R6)
// ---------------------------------------------------------------------------
#define BM 128
#define BN 128
#define BK 32
#define CHUNKS (D_MODEL / BK)
#define TPAD 40
#define TILE_B (128 * TPAD * 2)
#define STAGE_B (4 * TILE_B)
#define GEMM_SMEM (2 * STAGE_B)        // 81920

template <int MODE>
__device__ __forceinline__ void gemm_body(
    const __nv_bfloat16* __restrict__ Ah, const __nv_bfloat16* __restrict__ Al,
    const __nv_bfloat16* __restrict__ Bh, const __nv_bfloat16* __restrict__ Bl,
    __nv_bfloat16* __restrict__ Ch, __nv_bfloat16* __restrict__ Cl,
    float* __restrict__ Cf, const int bm, const int bn)
{
    extern __shared__ __align__(128) char smem[];
    const uint32_t sbase = smem_u32(smem);
    const int tid  = threadIdx.x;
    const int wid  = tid >> 5;
    const int lane = tid & 31;
    const int K = D_MODEL;

    const int warp_m = wid >> 2;
    const int warp_n = wid & 3;

    auto load_stage = [&](int chunk, int s) {
        const uint32_t st = sbase + s * STAGE_B;
        const int k0 = chunk * BK;
#pragma unroll
        for (int u = 0; u < 8; u++) {
            const int id = u * 256 + tid;
            const int t = id >> 9;
            const int idx = id & 511;
            const int row = idx >> 2;
            const int c = idx & 3;
            const __nv_bfloat16* g;
            int grow;
            if (t == 0)      { g = Ah; grow = bm + row; }
            else if (t == 1) { g = Al; grow = bm + row; }
            else if (t == 2) { g = Bh; grow = bn + row; }
            else             { g = Bl; grow = bn + row; }
            const __nv_bfloat16* gaddr = g + (size_t)grow * K + k0 + c * 8;
            const uint32_t saddr = st + t * TILE_B + row * (TPAD * 2) + c * 16;
            CP_ASYNC16(saddr, gaddr);
        }
        CP_COMMIT();
    };

    load_stage(0, 0);
    load_stage(1, 1);

    float acc[4][4][4];
#pragma unroll
    for (int i = 0; i < 4; i++)
#pragma unroll
        for (int j = 0; j < 4; j++)
#pragma unroll
            for (int r = 0; r < 4; r++) acc[i][j][r] = 0.0f;

    const int a_row = warp_m * 64 + (lane & 15);
    const uint32_t a_off = a_row * (TPAD * 2) + (lane >> 4) * 16;
    const int b_row = warp_n * 32 + ((lane >> 4) & 1) * 8 + (lane & 7);
    const uint32_t b_off = b_row * (TPAD * 2) + ((lane >> 3) & 1) * 16;

    for (int chunk = 0; chunk < CHUNKS; chunk++) {
        const int s = chunk & 1;
        if (chunk < CHUNKS - 1) CP_WAIT(1);
        else                    CP_WAIT(0);
        __syncthreads();
        const uint32_t st = sbase + s * STAGE_B;
        const uint32_t aH = st + a_off;
        const uint32_t aL = st + TILE_B + a_off;
        const uint32_t bH = st + 2 * TILE_B + b_off;
        const uint32_t bL = st + 3 * TILE_B + b_off;

#pragma unroll
        for (int ks = 0; ks < 2; ks++) {
            const uint32_t kb = ks * 32;
            uint32_t fAH[4][4], fAL[4][4], fBH[4][2], fBL[4][2];
#pragma unroll
            for (int mt = 0; mt < 4; mt++) {
                LDMATRIX_X4(fAH[mt][0], fAH[mt][1], fAH[mt][2], fAH[mt][3],
                            aH + mt * 16 * (TPAD * 2) + kb);
                LDMATRIX_X4(fAL[mt][0], fAL[mt][1], fAL[mt][2], fAL[mt][3],
                            aL + mt * 16 * (TPAD * 2) + kb);
            }
#pragma unroll
            for (int np = 0; np < 2; np++) {
                LDMATRIX_X4(fBH[2 * np][0], fBH[2 * np][1],
                            fBH[2 * np + 1][0], fBH[2 * np + 1][1],
                            bH + np * 16 * (TPAD * 2) + kb);
                LDMATRIX_X4(fBL[2 * np][0], fBL[2 * np][1],
                            fBL[2 * np + 1][0], fBL[2 * np + 1][1],
                            bL + np * 16 * (TPAD * 2) + kb);
            }
#pragma unroll
            for (int mt = 0; mt < 4; mt++)
#pragma unroll
                for (int nt = 0; nt < 4; nt++) {
                    MMA16816(acc[mt][nt], fAH[mt][0], fAH[mt][1], fAH[mt][2],
                             fAH[mt][3], fBH[nt][0], fBH[nt][1]);
                    MMA16816(acc[mt][nt], fAH[mt][0], fAH[mt][1], fAH[mt][2],
                             fAH[mt][3], fBL[nt][0], fBL[nt][1]);
                    MMA16816(acc[mt][nt], fAL[mt][0], fAL[mt][1], fAL[mt][2],
                             fAL[mt][3], fBH[nt][0], fBH[nt][1]);
                }
        }
        __syncthreads();
        if (chunk + 2 < CHUNKS) load_stage(chunk + 2, s);
    }

#pragma unroll
    for (int mt = 0; mt < 4; mt++) {
#pragma unroll
        for (int half = 0; half < 2; half++) {
            const int m = bm + warp_m * 64 + mt * 16 + (lane >> 2) + half * 8;
#pragma unroll
            for (int nt = 0; nt < 4; nt++) {
                const int n = bn + warp_n * 32 + nt * 8 + (lane & 3) * 2;
                const float v0 = acc[mt][nt][2 * half];
                const float v1 = acc[mt][nt][2 * half + 1];
                if (MODE == 0) {
                    const int b = m >> 11;
                    const int sq = m & 2047;
                    const int h = n >> 6;
                    const int dd = n & 63;
                    const size_t idx =
                        ((size_t)((b * NHEAD + h) * SEQ + sq) << 6) + dd;
                    uint32_t ph, pl;
                    split2(v0, v1, ph, pl);
                    *(uint32_t*)&Ch[idx] = ph;
                    *(uint32_t*)&Cl[idx] = pl;
                } else {
                    const size_t idx = (size_t)m * D_MODEL + n;
                    *(float2*)&Cf[idx] = make_float2(v0, v1);
                }
            }
        }
    }
}

__global__ void __launch_bounds__(256, 2) gemm_qkv_kernel(
    const __nv_bfloat16* __restrict__ xh, const __nv_bfloat16* __restrict__ xl,
    const __nv_bfloat16* __restrict__ wqh, const __nv_bfloat16* __restrict__ wql,
    const __nv_bfloat16* __restrict__ wkh, const __nv_bfloat16* __restrict__ wkl,
    const __nv_bfloat16* __restrict__ wvh, const __nv_bfloat16* __restrict__ wvl,
    __nv_bfloat16* __restrict__ qh, __nv_bfloat16* __restrict__ ql,
    __nv_bfloat16* __restrict__ kh, __nv_bfloat16* __restrict__ kl,
    __nv_bfloat16* __restrict__ vh, __nv_bfloat16* __restrict__ vl)
{
    const int proj = blockIdx.x >> 3;
    const int bn = (blockIdx.x & 7) * BN;
    const int bm = blockIdx.y * BM;
    const __nv_bfloat16* Bh = (proj == 0) ? wqh : (proj == 1) ? wkh : wvh;
    const __nv_bfloat16* Bl = (proj == 0) ? wql : (proj == 1) ? wkl : wvl;
    __nv_bfloat16* Ch = (proj == 0) ? qh : (proj == 1) ? kh : vh;
    __nv_bfloat16* Cl = (proj == 0) ? ql : (proj == 1) ? kl : vl;
    gemm_body<0>(xh, xl, Bh, Bl, Ch, Cl, nullptr, bm, bn);
}

__global__ void __launch_bounds__(256, 2) gemm_out_kernel(
    const __nv_bfloat16* __restrict__ ah, const __nv_bfloat16* __restrict__ al,
    const __nv_bfloat16* __restrict__ woh, const __nv_bfloat16* __restrict__ wol,
    float* __restrict__ out)
{
    gemm_body<1>(ah, al, woh, wol, nullptr, nullptr, out,
                 blockIdx.y * BM, blockIdx.x * BN);
}

// ---------------------------------------------------------------------------
// Tensor-core causal flash attention (bf16 hi/lo split, fp32 accum).
// 128 threads / 64 q-rows per CTA, 3 CTAs/SM target; reversed qb schedule.
// ---------------------------------------------------------------------------
#define ATPAD 72
#define AT_STRIDE (ATPAD * 2)          // 144 bytes/row
#define AT_TILE_B (64 * AT_STRIDE)     // 9216
#define AT_STAGE_B (4 * AT_TILE_B)     // 36864 (Kh,Kl,Vh,Vl)
#define ATTN_SMEM (2 * AT_STAGE_B)     // 73728

__global__ void __launch_bounds__(128, 3) attn_mma_kernel(
    const __nv_bfloat16* __restrict__ Qh, const __nv_bfloat16* __restrict__ Ql,
    const __nv_bfloat16* __restrict__ Kh, const __nv_bfloat16* __restrict__ Kl,
    const __nv_bfloat16* __restrict__ Vh, const __nv_bfloat16* __restrict__ Vl,
    __nv_bfloat16* __restrict__ Ah, __nv_bfloat16* __restrict__ Al)
{
    extern __shared__ __align__(128) char smem[];
    const uint32_t sbase = smem_u32(smem);
    const int tid  = threadIdx.x;
    const int wid  = tid >> 5;
    const int lane = tid & 31;
    const int bh = blockIdx.y;
    const int qb = (int)gridDim.x - 1 - (int)blockIdx.x;   // heavy CTAs first
    const int q0 = qb * 64;
    const size_t base_off = (size_t)bh * SEQ * DKH;

    // ---- load Q tile (64x64 hi/lo) into stage-0 smem, then to registers
#pragma unroll
    for (int u = 0; u < 8; u++) {
        const int id = u * 128 + tid;      // 0..1023
        const int t = id >> 9;             // 0 hi, 1 lo
        const int idx = id & 511;
        const int row = idx >> 3;
        const int c = idx & 7;
        const __nv_bfloat16* g = t ? Ql : Qh;
        CP_ASYNC16(sbase + t * (64 * AT_STRIDE) + row * AT_STRIDE + c * 16,
                   g + base_off + (size_t)(q0 + row) * DKH + c * 8);
    }
    CP_COMMIT();
    CP_WAIT(0);
    __syncthreads();

    uint32_t Qh_[4][4], Ql_[4][4];
    {
        const uint32_t qa =
            sbase + (16 * wid + (lane & 15)) * AT_STRIDE + (lane >> 4) * 16;
#pragma unroll
        for (int ks = 0; ks < 4; ks++) {
            LDMATRIX_X4(Qh_[ks][0], Qh_[ks][1], Qh_[ks][2], Qh_[ks][3],
                        qa + ks * 32);
            LDMATRIX_X4(Ql_[ks][0], Ql_[ks][1], Ql_[ks][2], Ql_[ks][3],
                        qa + 64 * AT_STRIDE + ks * 32);
        }
    }
    __syncthreads();   // Q consumed; stage 0 reusable

    auto load_kv = [&](int jt, int buf) {
        const uint32_t st = sbase + buf * AT_STAGE_B;
        const int k0 = jt * 64;
#pragma unroll
        for (int u = 0; u < 16; u++) {
            const int id = u * 128 + tid;   // 0..2047
            const int t = id >> 9;          // 0:Kh 1:Kl 2:Vh 3:Vl
            const int idx = id & 511;
            const int row = idx >> 3;
            const int c = idx & 7;
            const __nv_bfloat16* g = (t == 0) ? Kh : (t == 1) ? Kl
                                     : (t == 2) ? Vh : Vl;
            CP_ASYNC16(st + t * AT_TILE_B + row * AT_STRIDE + c * 16,
                       g + base_off + (size_t)(k0 + row) * DKH + c * 8);
        }
        CP_COMMIT();
    };

    float O_[8][4];
#pragma unroll
    for (int i = 0; i < 8; i++)
#pragma unroll
        for (int j = 0; j < 4; j++) O_[i][j] = 0.0f;
    float m_lo = -1e30f, m_hi = -1e30f, l_lo = 0.0f, l_hi = 0.0f;

    const int row_lo = q0 + 16 * wid + (lane >> 2);
    const int row_hi = row_lo + 8;
    const uint32_t b_off =
        (((lane >> 4) & 1) * 8 + (lane & 7)) * AT_STRIDE + ((lane >> 3) & 1) * 16;
    const uint32_t v_off = (lane & 15) * AT_STRIDE + (lane >> 4) * 16;

    const int jmax = qb;
    load_kv(0, 0);

    for (int jt = 0; jt <= jmax; jt++) {
        if (jt < jmax) { load_kv(jt + 1, (jt + 1) & 1); CP_WAIT(1); }
        else           { CP_WAIT(0); }
        __syncthreads();
        const uint32_t st = sbase + (jt & 1) * AT_STAGE_B;

        // ---- S = Q K^T (3-pass split, interleaved accumulator pairs)
        float S_[8][4];
#pragma unroll
        for (int i = 0; i < 8; i++)
#pragma unroll
            for (int j = 0; j < 4; j++) S_[i][j] = 0.0f;

#pragma unroll
        for (int ks = 0; ks < 4; ks++)
#pragma unroll
            for (int np = 0; np < 4; np++) {
                uint32_t f0, f1, f2, f3, g0, g1, g2, g3;
                const uint32_t ka = st + np * 16 * AT_STRIDE + b_off + ks * 32;
                LDMATRIX_X4(f0, f1, f2, f3, ka);
                LDMATRIX_X4(g0, g1, g2, g3, ka + AT_TILE_B);
                MMA16816(S_[2 * np], Qh_[ks][0], Qh_[ks][1], Qh_[ks][2],
                         Qh_[ks][3], f0, f1);
                MMA16816(S_[2 * np + 1], Qh_[ks][0], Qh_[ks][1], Qh_[ks][2],
                         Qh_[ks][3], f2, f3);
                MMA16816(S_[2 * np], Qh_[ks][0], Qh_[ks][1], Qh_[ks][2],
                         Qh_[ks][3], g0, g1);
                MMA16816(S_[2 * np + 1], Qh_[ks][0], Qh_[ks][1], Qh_[ks][2],
                         Qh_[ks][3], g2, g3);
                MMA16816(S_[2 * np], Ql_[ks][0], Ql_[ks][1], Ql_[ks][2],
                         Ql_[ks][3], f0, f1);
                MMA16816(S_[2 * np + 1], Ql_[ks][0], Ql_[ks][1], Ql_[ks][2],
                         Ql_[ks][3], f2, f3);
            }

        // ---- scale + causal mask
        const int k0g = jt * 64;
#pragma unroll
        for (int nt = 0; nt < 8; nt++) {
            const int col = k0g + 8 * nt + 2 * (lane & 3);
            S_[nt][0] = (col     > row_lo) ? -1e30f : S_[nt][0] * 0.125f;
            S_[nt][1] = (col + 1 > row_lo) ? -1e30f : S_[nt][1] * 0.125f;
            S_[nt][2] = (col     > row_hi) ? -1e30f : S_[nt][2] * 0.125f;
            S_[nt][3] = (col + 1 > row_hi) ? -1e30f : S_[nt][3] * 0.125f;
        }

        // ---- online softmax
        float rmax_lo = -1e30f, rmax_hi = -1e30f;
#pragma unroll
        for (int nt = 0; nt < 8; nt++) {
            rmax_lo = fmaxf(rmax_lo, fmaxf(S_[nt][0], S_[nt][1]));
            rmax_hi = fmaxf(rmax_hi, fmaxf(S_[nt][2], S_[nt][3]));
        }
        rmax_lo = fmaxf(rmax_lo, __shfl_xor_sync(0xffffffffu, rmax_lo, 1));
        rmax_lo = fmaxf(rmax_lo, __shfl_xor_sync(0xffffffffu, rmax_lo, 2));
        rmax_hi = fmaxf(rmax_hi, __shfl_xor_sync(0xffffffffu, rmax_hi, 1));
        rmax_hi = fmaxf(rmax_hi, __shfl_xor_sync(0xffffffffu, rmax_hi, 2));

        const float mn_lo = fmaxf(m_lo, rmax_lo);
        const float mn_hi = fmaxf(m_hi, rmax_hi);
        const float al_lo = __expf(m_lo - mn_lo);
        const float al_hi = __expf(m_hi - mn_hi);
        m_lo = mn_lo; m_hi = mn_hi;

        float rs_lo = 0.0f, rs_hi = 0.0f;
#pragma unroll
        for (int nt = 0; nt < 8; nt++) {
            S_[nt][0] = __expf(S_[nt][0] - m_lo);
            S_[nt][1] = __expf(S_[nt][1] - m_lo);
            S_[nt][2] = __expf(S_[nt][2] - m_hi);
            S_[nt][3] = __expf(S_[nt][3] - m_hi);
            rs_lo += S_[nt][0] + S_[nt][1];
            rs_hi += S_[nt][2] + S_[nt][3];
        }
        rs_lo += __shfl_xor_sync(0xffffffffu, rs_lo, 1);
        rs_lo += __shfl_xor_sync(0xffffffffu, rs_lo, 2);
        rs_hi += __shfl_xor_sync(0xffffffffu, rs_hi, 1);
        rs_hi += __shfl_xor_sync(0xffffffffu, rs_hi, 2);
        l_lo = l_lo * al_lo + rs_lo;
        l_hi = l_hi * al_hi + rs_hi;

#pragma unroll
        for (int nt = 0; nt < 8; nt++) {
            O_[nt][0] *= al_lo; O_[nt][1] *= al_lo;
            O_[nt][2] *= al_hi; O_[nt][3] *= al_hi;
        }

        // ---- O += P V (interleaved accumulator pairs)
#pragma unroll
        for (int kp = 0; kp < 4; kp++) {
            uint32_t Ph[4], Pl[4];
            split2(S_[2 * kp][0],     S_[2 * kp][1],     Ph[0], Pl[0]);
            split2(S_[2 * kp][2],     S_[2 * kp][3],     Ph[1], Pl[1]);
            split2(S_[2 * kp + 1][0], S_[2 * kp + 1][1], Ph[2], Pl[2]);
            split2(S_[2 * kp + 1][2], S_[2 * kp + 1][3], Ph[3], Pl[3]);
#pragma unroll
            for (int dp = 0; dp < 4; dp++) {
                uint32_t v0, v1, v2, v3, w0, w1, w2, w3;
                const uint32_t va = st + 2 * AT_TILE_B +
                                    kp * 16 * AT_STRIDE + v_off + dp * 32;
                LDMATRIX_X4_T(v0, v1, v2, v3, va);
                LDMATRIX_X4_T(w0, w1, w2, w3, va + AT_TILE_B);
                MMA16816(O_[2 * dp], Ph[0], Ph[1], Ph[2], Ph[3], v0, v1);
                MMA16816(O_[2 * dp + 1], Ph[0], Ph[1], Ph[2], Ph[3], v2, v3);
                MMA16816(O_[2 * dp], Ph[0], Ph[1], Ph[2], Ph[3], w0, w1);
                MMA16816(O_[2 * dp + 1], Ph[0], Ph[1], Ph[2], Ph[3], w2, w3);
                MMA16816(O_[2 * dp], Pl[0], Pl[1], Pl[2], Pl[3], v0, v1);
                MMA16816(O_[2 * dp + 1], Pl[0], Pl[1], Pl[2], Pl[3], v2, v3);
            }
        }
        __syncthreads();
    }

    // ---- epilogue
    const float inv_lo = 1.0f / l_lo;
    const float inv_hi = 1.0f / l_hi;
    const int b = bh >> 4;
    const int hh = bh & 15;
#pragma unroll
    for (int nt = 0; nt < 8; nt++) {
        const int col = hh * DKH + 8 * nt + 2 * (lane & 3);
        uint32_t ph, pl;
        split2(O_[nt][0] * inv_lo, O_[nt][1] * inv_lo, ph, pl);
        const size_t i0 = (size_t)(b * SEQ + row_lo) * D_MODEL + col;
        *(uint32_t*)&Ah[i0] = ph;
        *(uint32_t*)&Al[i0] = pl;
        split2(O_[nt][2] * inv_hi, O_[nt][3] * inv_hi, ph, pl);
        const size_t i1 = (size_t)(b * SEQ + row_hi) * D_MODEL + col;
        *(uint32_t*)&Ah[i1] = ph;
        *(uint32_t*)&Al[i1] = pl;
    }
}

// ---------------------------------------------------------------------------
// launch
// ---------------------------------------------------------------------------
extern "C" void kernel_launch(void* const* d_in, const int* in_sizes, int n_in,
                              void* d_out, int out_size)
{
    (void)in_sizes; (void)n_in; (void)out_size;
    const float* x  = (const float*)d_in[0];
    const float* wq = (const float*)d_in[1];
    const float* wk = (const float*)d_in[2];
    const float* wv = (const float*)d_in[3];
    const float* wo = (const float*)d_in[4];
    float* out = (float*)d_out;

    __nv_bfloat16 *xh, *xl, *qh, *ql, *kh, *kl, *vh, *vl, *ah, *al;
    __nv_bfloat16 *wqh, *wql, *wkh, *wkl, *wvh, *wvl, *woh, *wol;
    cudaGetSymbolAddress((void**)&xh, g_xh);
    cudaGetSymbolAddress((void**)&xl, g_xl);
    cudaGetSymbolAddress((void**)&qh, g_qh);
    cudaGetSymbolAddress((void**)&ql, g_ql);
    cudaGetSymbolAddress((void**)&kh, g_kh);
    cudaGetSymbolAddress((void**)&kl, g_kl);
    cudaGetSymbolAddress((void**)&vh, g_vh);
    cudaGetSymbolAddress((void**)&vl, g_vl);
    cudaGetSymbolAddress((void**)&ah, g_ah);
    cudaGetSymbolAddress((void**)&al, g_al);
    cudaGetSymbolAddress((void**)&wqh, g_wqh);
    cudaGetSymbolAddress((void**)&wql, g_wql);
    cudaGetSymbolAddress((void**)&wkh, g_wkh);
    cudaGetSymbolAddress((void**)&wkl, g_wkl);
    cudaGetSymbolAddress((void**)&wvh, g_wvh);
    cudaGetSymbolAddress((void**)&wvl, g_wvl);
    cudaGetSymbolAddress((void**)&woh, g_woh);
    cudaGetSymbolAddress((void**)&wol, g_wol);

    cudaFuncSetAttribute(gemm_qkv_kernel,
                         cudaFuncAttributeMaxDynamicSharedMemorySize, GEMM_SMEM);
    cudaFuncSetAttribute(gemm_out_kernel,
                         cudaFuncAttributeMaxDynamicSharedMemorySize, GEMM_SMEM);
    cudaFuncSetAttribute(attn_mma_kernel,
                         cudaFuncAttributeMaxDynamicSharedMemorySize, ATTN_SMEM);

    const int nx4 = MTOK * D_MODEL / 4;
    split_kernel<<<(nx4 + 255) / 256, 256>>>(x, xh, xl, nx4);
    split4_kernel<<<(4 * NW4 + 255) / 256, 256>>>(
        wq, wk, wv, wo, wqh, wql, wkh, wkl, wvh, wvl, woh, wol);

    gemm_qkv_kernel<<<dim3(24, MTOK / BM), 256, GEMM_SMEM>>>(
        xh, xl, wqh, wql, wkh, wkl, wvh, wvl, qh, ql, kh, kl, vh, vl);

    attn_mma_kernel<<<dim3(SEQ / 64, BATCH * NHEAD), 128, ATTN_SMEM>>>(
        qh, ql, kh, kl, vh, vl, ah, al);

    gemm_out_kernel<<<dim3(D_MODEL / BN, MTOK / BM), 256, GEMM_SMEM>>>(
        ah, al, woh, wol, out);
}

// round 8
// speedup vs baseline: 3.5160x; 1.0699x over previous
#include <cuda_runtime.h>
#include <cuda_bf16.h>
#include <cstdint>
#include <math.h>

#define D_MODEL 1024
#define NHEAD 16
#define DKH 64
#define BATCH 4
#define SEQ 2048
#define MTOK (BATCH * SEQ)   // 8192

// ---------------------------------------------------------------------------
// Scratch (alloc-free rule: __device__ globals)
// ---------------------------------------------------------------------------
__device__ __nv_bfloat16 g_xh[MTOK * D_MODEL];
__device__ __nv_bfloat16 g_xl[MTOK * D_MODEL];
__device__ __nv_bfloat16 g_qh[MTOK * D_MODEL];   // [B,H,S,64]
__device__ __nv_bfloat16 g_ql[MTOK * D_MODEL];
__device__ __nv_bfloat16 g_kh[MTOK * D_MODEL];
__device__ __nv_bfloat16 g_kl[MTOK * D_MODEL];
__device__ __nv_bfloat16 g_vh[MTOK * D_MODEL];
__device__ __nv_bfloat16 g_vl[MTOK * D_MODEL];
__device__ __nv_bfloat16 g_ah[MTOK * D_MODEL];   // attn out [B,S,D]
__device__ __nv_bfloat16 g_al[MTOK * D_MODEL];
__device__ __nv_bfloat16 g_wqh[D_MODEL * D_MODEL];
__device__ __nv_bfloat16 g_wql[D_MODEL * D_MODEL];
__device__ __nv_bfloat16 g_wkh[D_MODEL * D_MODEL];
__device__ __nv_bfloat16 g_wkl[D_MODEL * D_MODEL];
__device__ __nv_bfloat16 g_wvh[D_MODEL * D_MODEL];
__device__ __nv_bfloat16 g_wvl[D_MODEL * D_MODEL];
__device__ __nv_bfloat16 g_woh[D_MODEL * D_MODEL];
__device__ __nv_bfloat16 g_wol[D_MODEL * D_MODEL];

// ---------------------------------------------------------------------------
// helpers (arch-portable only: cp.async / ldmatrix / mma.sync)
// ---------------------------------------------------------------------------
__device__ __forceinline__ uint32_t smem_u32(const void* p) {
    uint32_t a;
    asm("{ .reg .u64 t; cvta.to.shared.u64 t, %1; cvt.u32.u64 %0, t; }"
        : "=r"(a) : "l"(p));
    return a;
}

#define LDMATRIX_X4(r0, r1, r2, r3, addr) \
    asm volatile("ldmatrix.sync.aligned.m8n8.x4.shared.b16 {%0,%1,%2,%3}, [%4];" \
        : "=r"(r0), "=r"(r1), "=r"(r2), "=r"(r3) : "r"(addr))

#define LDMATRIX_X4_T(r0, r1, r2, r3, addr) \
    asm volatile("ldmatrix.sync.aligned.m8n8.x4.trans.shared.b16 {%0,%1,%2,%3}, [%4];" \
        : "=r"(r0), "=r"(r1), "=r"(r2), "=r"(r3) : "r"(addr))

#define MMA16816(d, a0, a1, a2, a3, b0, b1) \
    asm volatile("mma.sync.aligned.m16n8k16.row.col.f32.bf16.bf16.f32 " \
        "{%0,%1,%2,%3}, {%4,%5,%6,%7}, {%8,%9}, {%0,%1,%2,%3};" \
        : "+f"((d)[0]), "+f"((d)[1]), "+f"((d)[2]), "+f"((d)[3]) \
        : "r"(a0), "r"(a1), "r"(a2), "r"(a3), "r"(b0), "r"(b1))

#define CP_ASYNC16(saddr, gaddr) \
    asm volatile("cp.async.cg.shared.global [%0], [%1], 16;" \
        :: "r"(saddr), "l"(gaddr))
#define CP_COMMIT() asm volatile("cp.async.commit_group;" ::: "memory")
#define CP_WAIT(n)  asm volatile("cp.async.wait_group %0;" :: "n"(n) : "memory")

#define PACK_BF16X2(r, lo, hi) \
    asm("cvt.rn.bf16x2.f32 %0, %1, %2;" : "=r"(r) : "f"(hi), "f"(lo))

__device__ __forceinline__ void split2(float v0, float v1,
                                       uint32_t& ph, uint32_t& pl) {
    PACK_BF16X2(ph, v0, v1);
    const float f0 = __uint_as_float(ph << 16);
    const float f1 = __uint_as_float(ph & 0xffff0000u);
    PACK_BF16X2(pl, v0 - f0, v1 - f1);
}

// ---------------------------------------------------------------------------
// fp32 -> bf16 hi/lo splits
// ---------------------------------------------------------------------------
__global__ void __launch_bounds__(256) split_kernel(
    const float* __restrict__ in,
    __nv_bfloat16* __restrict__ hi, __nv_bfloat16* __restrict__ lo, int n4)
{
    int i = blockIdx.x * 256 + threadIdx.x;
    if (i >= n4) return;
    float4 v = ((const float4*)in)[i];
    uint32_t h01, l01, h23, l23;
    split2(v.x, v.y, h01, l01);
    split2(v.z, v.w, h23, l23);
    ((uint32_t*)hi)[2 * i]     = h01;
    ((uint32_t*)hi)[2 * i + 1] = h23;
    ((uint32_t*)lo)[2 * i]     = l01;
    ((uint32_t*)lo)[2 * i + 1] = l23;
}

#define NW4 (D_MODEL * D_MODEL / 4)

__global__ void __launch_bounds__(256) split4_kernel(
    const float* __restrict__ w0, const float* __restrict__ w1,
    const float* __restrict__ w2, const float* __restrict__ w3,
    __nv_bfloat16* __restrict__ h0, __nv_bfloat16* __restrict__ l0,
    __nv_bfloat16* __restrict__ h1, __nv_bfloat16* __restrict__ l1,
    __nv_bfloat16* __restrict__ h2, __nv_bfloat16* __restrict__ l2,
    __nv_bfloat16* __restrict__ h3, __nv_bfloat16* __restrict__ l3)
{
    int id = blockIdx.x * 256 + threadIdx.x;
    const int which = id / NW4;
    const int i = id - which * NW4;
    const float* in = (which == 0) ? w0 : (which == 1) ? w1
                      : (which == 2) ? w2 : w3;
    __nv_bfloat16* hi = (which == 0) ? h0 : (which == 1) ? h1
                        : (which == 2) ? h2 : h3;
    __nv_bfloat16* lo = (which == 0) ? l0 : (which == 1) ? l1
                        : (which == 2) ? l2 : l3;
    float4 v = ((const float4*)in)[i];
    uint32_t h01, l01, h23, l23;
    split2(v.x, v.y, h01, l01);
    split2(v.z, v.w, h23, l23);
    ((uint32_t*)hi)[2 * i]     = h01;
    ((uint32_t*)hi)[2 * i + 1] = h23;
    ((uint32_t*)lo)[2 * i]     = l01;
    ((uint32_t*)lo)[2 * i + 1] = l23;
}

// ---------------------------------------------------------------------------
// mma.sync bf16-split GEMM body: C[m,n] = sum_k A[m,k]*B[n,k]
// 128x128 tile/CTA, BK=32, XOR-swizzled smem (no padding), 3-stage pipeline,
// 2 CTAs/SM. Swizzle: addr = row*64 + ((c ^ ((row>>1)&3))<<4), c = 16B block.
// ---------------------------------------------------------------------------
#define BM 128
#define BN 128
#define BK 32
#define CHUNKS (D_MODEL / BK)          // 32
#define TILE_B (128 * 64)              // 8192 bytes, swizzled
#define STAGE_B (4 * TILE_B)           // 32768 (Ah,Al,Bh,Bl)
#define GEMM_SMEM (3 * STAGE_B)        // 98304

template <int MODE>
__device__ __forceinline__ void gemm_body(
    const __nv_bfloat16* __restrict__ Ah, const __nv_bfloat16* __restrict__ Al,
    const __nv_bfloat16* __restrict__ Bh, const __nv_bfloat16* __restrict__ Bl,
    __nv_bfloat16* __restrict__ Ch, __nv_bfloat16* __restrict__ Cl,
    float* __restrict__ Cf, const int bm, const int bn)
{
    extern __shared__ __align__(128) char smem[];
    const uint32_t sbase = smem_u32(smem);
    const int tid  = threadIdx.x;
    const int wid  = tid >> 5;
    const int lane = tid & 31;
    const int K = D_MODEL;

    const int warp_m = wid >> 2;
    const int warp_n = wid & 3;

    auto load_stage = [&](int chunk, int s) {
        const uint32_t st = sbase + s * STAGE_B;
        const int k0 = chunk * BK;
#pragma unroll
        for (int u = 0; u < 8; u++) {
            const int id = u * 256 + tid;      // 0..2047
            const int t = id >> 9;             // 0:Ah 1:Al 2:Bh 3:Bl
            const int idx = id & 511;
            const int row = idx >> 2;          // 0..127
            const int c = idx & 3;             // 16B block
            const __nv_bfloat16* g;
            int grow;
            if (t == 0)      { g = Ah; grow = bm + row; }
            else if (t == 1) { g = Al; grow = bm + row; }
            else if (t == 2) { g = Bh; grow = bn + row; }
            else             { g = Bl; grow = bn + row; }
            const __nv_bfloat16* gaddr = g + (size_t)grow * K + k0 + c * 8;
            const uint32_t saddr = st + t * TILE_B + row * 64 +
                                   (((uint32_t)(c ^ ((row >> 1) & 3))) << 4);
            CP_ASYNC16(saddr, gaddr);
        }
        CP_COMMIT();
    };

    load_stage(0, 0);
    load_stage(1, 1);
    load_stage(2, 2);

    float acc[4][4][4];
#pragma unroll
    for (int i = 0; i < 4; i++)
#pragma unroll
        for (int j = 0; j < 4; j++)
#pragma unroll
            for (int r = 0; r < 4; r++) acc[i][j][r] = 0.0f;

    // ldmatrix per-lane swizzled base offsets (ks handled by XOR (ks<<5))
    const int a_row = warp_m * 64 + (lane & 15);
    const uint32_t a_off = (uint32_t)a_row * 64 +
        ((uint32_t)(((lane >> 4) ^ ((a_row >> 1) & 3))) << 4);
    const int b_row = warp_n * 32 + ((lane >> 4) & 1) * 8 + (lane & 7);
    const uint32_t b_off = (uint32_t)b_row * 64 +
        ((uint32_t)((((lane >> 3) & 1) ^ ((b_row >> 1) & 3))) << 4);

    int s = 0;
    for (int chunk = 0; chunk < CHUNKS; chunk++) {
        if (chunk < CHUNKS - 2)       CP_WAIT(2);
        else if (chunk == CHUNKS - 2) CP_WAIT(1);
        else                          CP_WAIT(0);
        __syncthreads();
        const uint32_t st = sbase + s * STAGE_B;
        const uint32_t aH = st + a_off;
        const uint32_t aL = st + TILE_B + a_off;
        const uint32_t bH = st + 2 * TILE_B + b_off;
        const uint32_t bL = st + 3 * TILE_B + b_off;

#pragma unroll
        for (int ks = 0; ks < 2; ks++) {
            const uint32_t kx = (uint32_t)ks << 5;
            uint32_t fAH[4][4], fAL[4][4], fBH[4][2], fBL[4][2];
#pragma unroll
            for (int mt = 0; mt < 4; mt++) {
                LDMATRIX_X4(fAH[mt][0], fAH[mt][1], fAH[mt][2], fAH[mt][3],
                            (aH + mt * 1024) ^ kx);
                LDMATRIX_X4(fAL[mt][0], fAL[mt][1], fAL[mt][2], fAL[mt][3],
                            (aL + mt * 1024) ^ kx);
            }
#pragma unroll
            for (int np = 0; np < 2; np++) {
                LDMATRIX_X4(fBH[2 * np][0], fBH[2 * np][1],
                            fBH[2 * np + 1][0], fBH[2 * np + 1][1],
                            (bH + np * 1024) ^ kx);
                LDMATRIX_X4(fBL[2 * np][0], fBL[2 * np][1],
                            fBL[2 * np + 1][0], fBL[2 * np + 1][1],
                            (bL + np * 1024) ^ kx);
            }
#pragma unroll
            for (int mt = 0; mt < 4; mt++)
#pragma unroll
                for (int nt = 0; nt < 4; nt++) {
                    MMA16816(acc[mt][nt], fAH[mt][0], fAH[mt][1], fAH[mt][2],
                             fAH[mt][3], fBH[nt][0], fBH[nt][1]);
                    MMA16816(acc[mt][nt], fAH[mt][0], fAH[mt][1], fAH[mt][2],
                             fAH[mt][3], fBL[nt][0], fBL[nt][1]);
                    MMA16816(acc[mt][nt], fAL[mt][0], fAL[mt][1], fAL[mt][2],
                             fAL[mt][3], fBH[nt][0], fBH[nt][1]);
                }
        }
        __syncthreads();
        if (chunk + 3 < CHUNKS) load_stage(chunk + 3, s);
        s = (s == 2) ? 0 : s + 1;
    }

#pragma unroll
    for (int mt = 0; mt < 4; mt++) {
#pragma unroll
        for (int half = 0; half < 2; half++) {
            const int m = bm + warp_m * 64 + mt * 16 + (lane >> 2) + half * 8;
#pragma unroll
            for (int nt = 0; nt < 4; nt++) {
                const int n = bn + warp_n * 32 + nt * 8 + (lane & 3) * 2;
                const float v0 = acc[mt][nt][2 * half];
                const float v1 = acc[mt][nt][2 * half + 1];
                if (MODE == 0) {
                    const int b = m >> 11;
                    const int sq = m & 2047;
                    const int h = n >> 6;
                    const int dd = n & 63;
                    const size_t idx =
                        ((size_t)((b * NHEAD + h) * SEQ + sq) << 6) + dd;
                    uint32_t ph, pl;
                    split2(v0, v1, ph, pl);
                    *(uint32_t*)&Ch[idx] = ph;
                    *(uint32_t*)&Cl[idx] = pl;
                } else {
                    const size_t idx = (size_t)m * D_MODEL + n;
                    *(float2*)&Cf[idx] = make_float2(v0, v1);
                }
            }
        }
    }
}

__global__ void __launch_bounds__(256, 2) gemm_qkv_kernel(
    const __nv_bfloat16* __restrict__ xh, const __nv_bfloat16* __restrict__ xl,
    const __nv_bfloat16* __restrict__ wqh, const __nv_bfloat16* __restrict__ wql,
    const __nv_bfloat16* __restrict__ wkh, const __nv_bfloat16* __restrict__ wkl,
    const __nv_bfloat16* __restrict__ wvh, const __nv_bfloat16* __restrict__ wvl,
    __nv_bfloat16* __restrict__ qh, __nv_bfloat16* __restrict__ ql,
    __nv_bfloat16* __restrict__ kh, __nv_bfloat16* __restrict__ kl,
    __nv_bfloat16* __restrict__ vh, __nv_bfloat16* __restrict__ vl)
{
    const int proj = blockIdx.x >> 3;
    const int bn = (blockIdx.x & 7) * BN;
    const int bm = blockIdx.y * BM;
    const __nv_bfloat16* Bh = (proj == 0) ? wqh : (proj == 1) ? wkh : wvh;
    const __nv_bfloat16* Bl = (proj == 0) ? wql : (proj == 1) ? wkl : wvl;
    __nv_bfloat16* Ch = (proj == 0) ? qh : (proj == 1) ? kh : vh;
    __nv_bfloat16* Cl = (proj == 0) ? ql : (proj == 1) ? kl : vl;
    gemm_body<0>(xh, xl, Bh, Bl, Ch, Cl, nullptr, bm, bn);
}

__global__ void __launch_bounds__(256, 2) gemm_out_kernel(
    const __nv_bfloat16* __restrict__ ah, const __nv_bfloat16* __restrict__ al,
    const __nv_bfloat16* __restrict__ woh, const __nv_bfloat16* __restrict__ wol,
    float* __restrict__ out)
{
    gemm_body<1>(ah, al, woh, wol, nullptr, nullptr, out,
                 blockIdx.y * BM, blockIdx.x * BN);
}

// ---------------------------------------------------------------------------
// Tensor-core causal flash attention (bf16 hi/lo split, fp32 accum).
// 128 threads / 64 q-rows per CTA, 3 CTAs/SM; reversed qb schedule.
// (unchanged from R7)
// ---------------------------------------------------------------------------
#define ATPAD 72
#define AT_STRIDE (ATPAD * 2)          // 144 bytes/row
#define AT_TILE_B (64 * AT_STRIDE)     // 9216
#define AT_STAGE_B (4 * AT_TILE_B)     // 36864 (Kh,Kl,Vh,Vl)
#define ATTN_SMEM (2 * AT_STAGE_B)     // 73728

__global__ void __launch_bounds__(128, 3) attn_mma_kernel(
    const __nv_bfloat16* __restrict__ Qh, const __nv_bfloat16* __restrict__ Ql,
    const __nv_bfloat16* __restrict__ Kh, const __nv_bfloat16* __restrict__ Kl,
    const __nv_bfloat16* __restrict__ Vh, const __nv_bfloat16* __restrict__ Vl,
    __nv_bfloat16* __restrict__ Ah, __nv_bfloat16* __restrict__ Al)
{
    extern __shared__ __align__(128) char smem[];
    const uint32_t sbase = smem_u32(smem);
    const int tid  = threadIdx.x;
    const int wid  = tid >> 5;
    const int lane = tid & 31;
    const int bh = blockIdx.y;
    const int qb = (int)gridDim.x - 1 - (int)blockIdx.x;   // heavy CTAs first
    const int q0 = qb * 64;
    const size_t base_off = (size_t)bh * SEQ * DKH;

#pragma unroll
    for (int u = 0; u < 8; u++) {
        const int id = u * 128 + tid;
        const int t = id >> 9;
        const int idx = id & 511;
        const int row = idx >> 3;
        const int c = idx & 7;
        const __nv_bfloat16* g = t ? Ql : Qh;
        CP_ASYNC16(sbase + t * (64 * AT_STRIDE) + row * AT_STRIDE + c * 16,
                   g + base_off + (size_t)(q0 + row) * DKH + c * 8);
    }
    CP_COMMIT();
    CP_WAIT(0);
    __syncthreads();

    uint32_t Qh_[4][4], Ql_[4][4];
    {
        const uint32_t qa =
            sbase + (16 * wid + (lane & 15)) * AT_STRIDE + (lane >> 4) * 16;
#pragma unroll
        for (int ks = 0; ks < 4; ks++) {
            LDMATRIX_X4(Qh_[ks][0], Qh_[ks][1], Qh_[ks][2], Qh_[ks][3],
                        qa + ks * 32);
            LDMATRIX_X4(Ql_[ks][0], Ql_[ks][1], Ql_[ks][2], Ql_[ks][3],
                        qa + 64 * AT_STRIDE + ks * 32);
        }
    }
    __syncthreads();

    auto load_kv = [&](int jt, int buf) {
        const uint32_t st = sbase + buf * AT_STAGE_B;
        const int k0 = jt * 64;
#pragma unroll
        for (int u = 0; u < 16; u++) {
            const int id = u * 128 + tid;
            const int t = id >> 9;
            const int idx = id & 511;
            const int row = idx >> 3;
            const int c = idx & 7;
            const __nv_bfloat16* g = (t == 0) ? Kh : (t == 1) ? Kl
                                     : (t == 2) ? Vh : Vl;
            CP_ASYNC16(st + t * AT_TILE_B + row * AT_STRIDE + c * 16,
                       g + base_off + (size_t)(k0 + row) * DKH + c * 8);
        }
        CP_COMMIT();
    };

    float O_[8][4];
#pragma unroll
    for (int i = 0; i < 8; i++)
#pragma unroll
        for (int j = 0; j < 4; j++) O_[i][j] = 0.0f;
    float m_lo = -1e30f, m_hi = -1e30f, l_lo = 0.0f, l_hi = 0.0f;

    const int row_lo = q0 + 16 * wid + (lane >> 2);
    const int row_hi = row_lo + 8;
    const uint32_t b_off =
        (((lane >> 4) & 1) * 8 + (lane & 7)) * AT_STRIDE + ((lane >> 3) & 1) * 16;
    const uint32_t v_off = (lane & 15) * AT_STRIDE + (lane >> 4) * 16;

    const int jmax = qb;
    load_kv(0, 0);

    for (int jt = 0; jt <= jmax; jt++) {
        if (jt < jmax) { load_kv(jt + 1, (jt + 1) & 1); CP_WAIT(1); }
        else           { CP_WAIT(0); }
        __syncthreads();
        const uint32_t st = sbase + (jt & 1) * AT_STAGE_B;

        float S_[8][4];
#pragma unroll
        for (int i = 0; i < 8; i++)
#pragma unroll
            for (int j = 0; j < 4; j++) S_[i][j] = 0.0f;

#pragma unroll
        for (int ks = 0; ks < 4; ks++)
#pragma unroll
            for (int np = 0; np < 4; np++) {
                uint32_t f0, f1, f2, f3, g0, g1, g2, g3;
                const uint32_t ka = st + np * 16 * AT_STRIDE + b_off + ks * 32;
                LDMATRIX_X4(f0, f1, f2, f3, ka);
                LDMATRIX_X4(g0, g1, g2, g3, ka + AT_TILE_B);
                MMA16816(S_[2 * np], Qh_[ks][0], Qh_[ks][1], Qh_[ks][2],
                         Qh_[ks][3], f0, f1);
                MMA16816(S_[2 * np + 1], Qh_[ks][0], Qh_[ks][1], Qh_[ks][2],
                         Qh_[ks][3], f2, f3);
                MMA16816(S_[2 * np], Qh_[ks][0], Qh_[ks][1], Qh_[ks][2],
                         Qh_[ks][3], g0, g1);
                MMA16816(S_[2 * np + 1], Qh_[ks][0], Qh_[ks][1], Qh_[ks][2],
                         Qh_[ks][3], g2, g3);
                MMA16816(S_[2 * np], Ql_[ks][0], Ql_[ks][1], Ql_[ks][2],
                         Ql_[ks][3], f0, f1);
                MMA16816(S_[2 * np + 1], Ql_[ks][0], Ql_[ks][1], Ql_[ks][2],
                         Ql_[ks][3], f2, f3);
            }

        const int k0g = jt * 64;
#pragma unroll
        for (int nt = 0; nt < 8; nt++) {
            const int col = k0g + 8 * nt + 2 * (lane & 3);
            S_[nt][0] = (col     > row_lo) ? -1e30f : S_[nt][0] * 0.125f;
            S_[nt][1] = (col + 1 > row_lo) ? -1e30f : S_[nt][1] * 0.125f;
            S_[nt][2] = (col     > row_hi) ? -1e30f : S_[nt][2] * 0.125f;
            S_[nt][3] = (col + 1 > row_hi) ? -1e30f : S_[nt][3] * 0.125f;
        }

        float rmax_lo = -1e30f, rmax_hi = -1e30f;
#pragma unroll
        for (int nt = 0; nt < 8; nt++) {
            rmax_lo = fmaxf(rmax_lo, fmaxf(S_[nt][0], S_[nt][1]));
            rmax_hi = fmaxf(rmax_hi, fmaxf(S_[nt][2], S_[nt][3]));
        }
        rmax_lo = fmaxf(rmax_lo, __shfl_xor_sync(0xffffffffu, rmax_lo, 1));
        rmax_lo = fmaxf(rmax_lo, __shfl_xor_sync(0xffffffffu, rmax_lo, 2));
        rmax_hi = fmaxf(rmax_hi, __shfl_xor_sync(0xffffffffu, rmax_hi, 1));
        rmax_hi = fmaxf(rmax_hi, __shfl_xor_sync(0xffffffffu, rmax_hi, 2));

        const float mn_lo = fmaxf(m_lo, rmax_lo);
        const float mn_hi = fmaxf(m_hi, rmax_hi);
        const float al_lo = __expf(m_lo - mn_lo);
        const float al_hi = __expf(m_hi - mn_hi);
        m_lo = mn_lo; m_hi = mn_hi;

        float rs_lo = 0.0f, rs_hi = 0.0f;
#pragma unroll
        for (int nt = 0; nt < 8; nt++) {
            S_[nt][0] = __expf(S_[nt][0] - m_lo);
            S_[nt][1] = __expf(S_[nt][1] - m_lo);
            S_[nt][2] = __expf(S_[nt][2] - m_hi);
            S_[nt][3] = __expf(S_[nt][3] - m_hi);
            rs_lo += S_[nt][0] + S_[nt][1];
            rs_hi += S_[nt][2] + S_[nt][3];
        }
        rs_lo += __shfl_xor_sync(0xffffffffu, rs_lo, 1);
        rs_lo += __shfl_xor_sync(0xffffffffu, rs_lo, 2);
        rs_hi += __shfl_xor_sync(0xffffffffu, rs_hi, 1);
        rs_hi += __shfl_xor_sync(0xffffffffu, rs_hi, 2);
        l_lo = l_lo * al_lo + rs_lo;
        l_hi = l_hi * al_hi + rs_hi;

#pragma unroll
        for (int nt = 0; nt < 8; nt++) {
            O_[nt][0] *= al_lo; O_[nt][1] *= al_lo;
            O_[nt][2] *= al_hi; O_[nt][3] *= al_hi;
        }

#pragma unroll
        for (int kp = 0; kp < 4; kp++) {
            uint32_t Ph[4], Pl[4];
            split2(S_[2 * kp][0],     S_[2 * kp][1],     Ph[0], Pl[0]);
            split2(S_[2 * kp][2],     S_[2 * kp][3],     Ph[1], Pl[1]);
            split2(S_[2 * kp + 1][0], S_[2 * kp + 1][1], Ph[2], Pl[2]);
            split2(S_[2 * kp + 1][2], S_[2 * kp + 1][3], Ph[3], Pl[3]);
#pragma unroll
            for (int dp = 0; dp < 4; dp++) {
                uint32_t v0, v1, v2, v3, w0, w1, w2, w3;
                const uint32_t va = st + 2 * AT_TILE_B +
                                    kp * 16 * AT_STRIDE + v_off + dp * 32;
                LDMATRIX_X4_T(v0, v1, v2, v3, va);
                LDMATRIX_X4_T(w0, w1, w2, w3, va + AT_TILE_B);
                MMA16816(O_[2 * dp], Ph[0], Ph[1], Ph[2], Ph[3], v0, v1);
                MMA16816(O_[2 * dp + 1], Ph[0], Ph[1], Ph[2], Ph[3], v2, v3);
                MMA16816(O_[2 * dp], Ph[0], Ph[1], Ph[2], Ph[3], w0, w1);
                MMA16816(O_[2 * dp + 1], Ph[0], Ph[1], Ph[2], Ph[3], w2, w3);
                MMA16816(O_[2 * dp], Pl[0], Pl[1], Pl[2], Pl[3], v0, v1);
                MMA16816(O_[2 * dp + 1], Pl[0], Pl[1], Pl[2], Pl[3], v2, v3);
            }
        }
        __syncthreads();
    }

    const float inv_lo = 1.0f / l_lo;
    const float inv_hi = 1.0f / l_hi;
    const int b = bh >> 4;
    const int hh = bh & 15;
#pragma unroll
    for (int nt = 0; nt < 8; nt++) {
        const int col = hh * DKH + 8 * nt + 2 * (lane & 3);
        uint32_t ph, pl;
        split2(O_[nt][0] * inv_lo, O_[nt][1] * inv_lo, ph, pl);
        const size_t i0 = (size_t)(b * SEQ + row_lo) * D_MODEL + col;
        *(uint32_t*)&Ah[i0] = ph;
        *(uint32_t*)&Al[i0] = pl;
        split2(O_[nt][2] * inv_hi, O_[nt][3] * inv_hi, ph, pl);
        const size_t i1 = (size_t)(b * SEQ + row_hi) * D_MODEL + col;
        *(uint32_t*)&Ah[i1] = ph;
        *(uint32_t*)&Al[i1] = pl;
    }
}

// ---------------------------------------------------------------------------
// launch
// ---------------------------------------------------------------------------
extern "C" void kernel_launch(void* const* d_in, const int* in_sizes, int n_in,
                              void* d_out, int out_size)
{
    (void)in_sizes; (void)n_in; (void)out_size;
    const float* x  = (const float*)d_in[0];
    const float* wq = (const float*)d_in[1];
    const float* wk = (const float*)d_in[2];
    const float* wv = (const float*)d_in[3];
    const float* wo = (const float*)d_in[4];
    float* out = (float*)d_out;

    __nv_bfloat16 *xh, *xl, *qh, *ql, *kh, *kl, *vh, *vl, *ah, *al;
    __nv_bfloat16 *wqh, *wql, *wkh, *wkl, *wvh, *wvl, *woh, *wol;
    cudaGetSymbolAddress((void**)&xh, g_xh);
    cudaGetSymbolAddress((void**)&xl, g_xl);
    cudaGetSymbolAddress((void**)&qh, g_qh);
    cudaGetSymbolAddress((void**)&ql, g_ql);
    cudaGetSymbolAddress((void**)&kh, g_kh);
    cudaGetSymbolAddress((void**)&kl, g_kl);
    cudaGetSymbolAddress((void**)&vh, g_vh);
    cudaGetSymbolAddress((void**)&vl, g_vl);
    cudaGetSymbolAddress((void**)&ah, g_ah);
    cudaGetSymbolAddress((void**)&al, g_al);
    cudaGetSymbolAddress((void**)&wqh, g_wqh);
    cudaGetSymbolAddress((void**)&wql, g_wql);
    cudaGetSymbolAddress((void**)&wkh, g_wkh);
    cudaGetSymbolAddress((void**)&wkl, g_wkl);
    cudaGetSymbolAddress((void**)&wvh, g_wvh);
    cudaGetSymbolAddress((void**)&wvl, g_wvl);
    cudaGetSymbolAddress((void**)&woh, g_woh);
    cudaGetSymbolAddress((void**)&wol, g_wol);

    cudaFuncSetAttribute(gemm_qkv_kernel,
                         cudaFuncAttributeMaxDynamicSharedMemorySize, GEMM_SMEM);
    cudaFuncSetAttribute(gemm_out_kernel,
                         cudaFuncAttributeMaxDynamicSharedMemorySize, GEMM_SMEM);
    cudaFuncSetAttribute(attn_mma_kernel,
                         cudaFuncAttributeMaxDynamicSharedMemorySize, ATTN_SMEM);

    const int nx4 = MTOK * D_MODEL / 4;
    split_kernel<<<(nx4 + 255) / 256, 256>>>(x, xh, xl, nx4);
    split4_kernel<<<(4 * NW4 + 255) / 256, 256>>>(
        wq, wk, wv, wo, wqh, wql, wkh, wkl, wvh, wvl, woh, wol);

    gemm_qkv_kernel<<<dim3(24, MTOK / BM), 256, GEMM_SMEM>>>(
        xh, xl, wqh, wql, wkh, wkl, wvh, wvl, qh, ql, kh, kl, vh, vl);

    attn_mma_kernel<<<dim3(SEQ / 64, BATCH * NHEAD), 128, ATTN_SMEM>>>(
        qh, ql, kh, kl, vh, vl, ah, al);

    gemm_out_kernel<<<dim3(D_MODEL / BN, MTOK / BM), 256, GEMM_SMEM>>>(
        ah, al, woh, wol, out);
}